// round 11
// baseline (speedup 1.0000x reference)
#include <cuda_runtime.h>
#include <cuda_bf16.h>
#include <math.h>

// Problem constants (shapes fixed by the dataset)
#define NMAX  100000
#define EMAX  1600000
#define F1    128
#define F2    64
#define SCAN_B 512
#define NBMAX ((NMAX + SCAN_B - 1) / SCAN_B)   // 196
#define NCHUNK 4

// ---------------- scratch (static device globals; no allocation allowed) ----
__device__ int    g_is64;                 // 1 if edge_index is int64, else int32
__device__ int    g_cnt[NMAX];
__device__ int    g_bsum[NBMAX];
__device__ int    g_boff[NBMAX];
__device__ int    g_rowstart[NMAX + 1];
__device__ int    g_cursor[NMAX];
__device__ float  g_dinv[NMAX];
__device__ int    g_csr[EMAX];
__device__ float4 g_h1s[(size_t)NMAX * F1 / 4];     // (x @ W1) * dinv[row]
__device__ float4 g_hidden[(size_t)NMAX * F1 / 4];  // relu(dinv*(sum)+b1)
__device__ float4 g_h2s[(size_t)NMAX * F2 / 4];     // (hidden @ W2) * dinv[row]

// ---------------- build kernels ---------------------------------------------

// Zero degree counts; thread 0 also probes edge_index dtype
// (int64 values < 2^31 have zero high words).
__global__ void k_init(const int* __restrict__ ei_raw, int N) {
    int i = blockIdx.x * blockDim.x + threadIdx.x;
    if (i < N) g_cnt[i] = 0;
    if (i == 0) {
        int any = 0;
        for (int j = 0; j < 64; j++) any |= ei_raw[2 * j + 1];
        g_is64 = (any == 0) ? 1 : 0;
    }
}

// Decode edge target (int32 or int64 per flag), validate, count in-degree.
__global__ void k_count(const void* __restrict__ ei_raw, int E, int N) {
    int e = blockIdx.x * blockDim.x + threadIdx.x;
    if (e >= E) return;
    int c;
    if (g_is64) {
        const long long* ei = (const long long*)ei_raw;
        c = (int)ei[(size_t)E + e];
    } else {
        const int* ei = (const int*)ei_raw;
        c = ei[(size_t)E + e];
    }
    if ((unsigned)c < (unsigned)N) atomicAdd(&g_cnt[c], 1);
}

// dinv depends only on counts — computed early so GEMM1 can fork off here.
__global__ void k_dinv(int N) {
    int i = blockIdx.x * blockDim.x + threadIdx.x;
    if (i < N) g_dinv[i] = rsqrtf((float)(g_cnt[i] + 1));   // +1 self loop
}

// Phase 1: per-block sums of counts.
__global__ void __launch_bounds__(SCAN_B) k_scan_partial(int N) {
    __shared__ int red[SCAN_B / 32];
    int b = blockIdx.x, tid = threadIdx.x;
    int i = b * SCAN_B + tid;
    int v = (i < N) ? g_cnt[i] : 0;
    for (int o = 16; o > 0; o >>= 1) v += __shfl_down_sync(0xffffffffu, v, o);
    if ((tid & 31) == 0) red[tid >> 5] = v;
    __syncthreads();
    if (tid < SCAN_B / 32) {
        int s = red[tid];
        for (int o = (SCAN_B / 64); o > 0; o >>= 1) s += __shfl_down_sync(0xffffu, s, o);
        if (tid == 0) g_bsum[b] = s;
    }
}

// Phase 2: single block scans block sums -> exclusive offsets; writes total.
__global__ void __launch_bounds__(256) k_scan_blk(int nb, int N) {
    __shared__ int sh[256];
    int tid = threadIdx.x;
    int v = (tid < nb) ? g_bsum[tid] : 0;
    sh[tid] = v;
    __syncthreads();
    for (int o = 1; o < 256; o <<= 1) {
        int t = (tid >= o) ? sh[tid - o] : 0;
        __syncthreads();
        sh[tid] += t;
        __syncthreads();
    }
    if (tid < nb) g_boff[tid] = sh[tid] - v;       // exclusive
    if (tid == 255) g_rowstart[N] = sh[255];       // total
}

// Phase 3: block-local exclusive scan + offset -> rowstart/cursor.
__global__ void __launch_bounds__(SCAN_B) k_scan_apply(int N) {
    __shared__ int sh[SCAN_B];
    int b = blockIdx.x, tid = threadIdx.x;
    int i = b * SCAN_B + tid;
    int v = (i < N) ? g_cnt[i] : 0;
    sh[tid] = v;
    __syncthreads();
    for (int o = 1; o < SCAN_B; o <<= 1) {
        int t = (tid >= o) ? sh[tid - o] : 0;
        __syncthreads();
        sh[tid] += t;
        __syncthreads();
    }
    if (i < N) {
        int base = g_boff[b] + sh[tid] - v;        // exclusive prefix
        g_rowstart[i] = base;
        g_cursor[i]   = base;
    }
}

// Fill CSR: decode edges directly (no staging), place source into target bucket.
__global__ void k_fill(const void* __restrict__ ei_raw, int E, int N) {
    int e = blockIdx.x * blockDim.x + threadIdx.x;
    if (e >= E) return;
    int r, c;
    if (g_is64) {
        const long long* ei = (const long long*)ei_raw;
        r = (int)ei[e];
        c = (int)ei[(size_t)E + e];
    } else {
        const int* ei = (const int*)ei_raw;
        r = ei[e];
        c = ei[(size_t)E + e];
    }
    if ((unsigned)r >= (unsigned)N || (unsigned)c >= (unsigned)N) return;
    int pos = atomicAdd(&g_cursor[c], 1);
    g_csr[pos] = r;
}

// ---------------- compute kernels -------------------------------------------

// Register-tiled GEMM1: h1s[n, fh+4*f4..+3] = (x[n] @ W1[:, ...]) * dinv[n].
// Block tile: 32 nodes x 64 features (half of F1, chosen by blockIdx.y).
__global__ void __launch_bounds__(256) k_gemm1(const float* __restrict__ x,
                                               const float* __restrict__ W1, int N) {
    __shared__ float4 W4s[F1][16];   // 32KB: W1[k][fh + 4*f4 .. +3]
    __shared__ float  xs[32][F1];    // 16KB
    int tid = threadIdx.x;
    int fh = blockIdx.y * 64;
    for (int idx = tid; idx < F1 * 16; idx += 256) {
        int k = idx >> 4, f4 = idx & 15;
        W4s[k][f4] = *(const float4*)(W1 + k * F1 + fh + 4 * f4);
    }
    int nd = tid >> 4;      // 0..15
    int f4 = tid & 15;      // 0..15 -> features fh+4*f4..+3
    int fo = (fh >> 2) + f4;
    int ntiles = (N + 31) >> 5;
    for (int t = blockIdx.x; t < ntiles; t += gridDim.x) {
        int base = t << 5;
        __syncthreads();   // xs reuse (also covers initial W load)
        for (int idx = tid; idx < 32 * (F1 / 4); idx += 256) {
            int r = idx >> 5, c4 = idx & 31;
            int nn = base + r;
            float4 v = (nn < N) ? *(const float4*)(x + (size_t)nn * F1 + 4 * c4)
                                : make_float4(0.f, 0.f, 0.f, 0.f);
            *(float4*)&xs[r][4 * c4] = v;
        }
        __syncthreads();
        float4 a0 = make_float4(0.f, 0.f, 0.f, 0.f);
        float4 a1 = make_float4(0.f, 0.f, 0.f, 0.f);
        #pragma unroll 4
        for (int k = 0; k < F1; k++) {
            float4 w = W4s[k][f4];
            float xa = xs[nd][k];
            float xb = xs[nd + 16][k];
            a0.x = fmaf(xa, w.x, a0.x); a0.y = fmaf(xa, w.y, a0.y);
            a0.z = fmaf(xa, w.z, a0.z); a0.w = fmaf(xa, w.w, a0.w);
            a1.x = fmaf(xb, w.x, a1.x); a1.y = fmaf(xb, w.y, a1.y);
            a1.z = fmaf(xb, w.z, a1.z); a1.w = fmaf(xb, w.w, a1.w);
        }
        int na = base + nd, nb = base + nd + 16;
        if (na < N) {
            float d = g_dinv[na];
            g_h1s[(size_t)na * (F1 / 4) + fo] =
                make_float4(a0.x * d, a0.y * d, a0.z * d, a0.w * d);
        }
        if (nb < N) {
            float d = g_dinv[nb];
            g_h1s[(size_t)nb * (F1 / 4) + fo] =
                make_float4(a1.x * d, a1.y * d, a1.z * d, a1.w * d);
        }
    }
}

// Aggregate layer 1 over node range [lo, hi): warp per node, 4-way unroll.
__global__ void __launch_bounds__(256) k_agg1(const float* __restrict__ b1,
                                              int lo, int hi) {
    int lane  = threadIdx.x & 31;
    int warp  = (blockIdx.x * blockDim.x + threadIdx.x) >> 5;
    int nwarp = (gridDim.x * blockDim.x) >> 5;
    float bx = b1[4 * lane + 0], by = b1[4 * lane + 1];
    float bz = b1[4 * lane + 2], bw = b1[4 * lane + 3];
    for (int n = lo + warp; n < hi; n += nwarp) {
        float4 acc = g_h1s[(size_t)n * (F1 / 4) + lane];   // self loop
        int s = g_rowstart[n], e = g_rowstart[n + 1];
        int i = s;
        for (; i + 4 <= e; i += 4) {
            int s0 = g_csr[i], s1 = g_csr[i + 1], s2 = g_csr[i + 2], s3 = g_csr[i + 3];
            float4 v0 = g_h1s[(size_t)s0 * (F1 / 4) + lane];
            float4 v1 = g_h1s[(size_t)s1 * (F1 / 4) + lane];
            float4 v2 = g_h1s[(size_t)s2 * (F1 / 4) + lane];
            float4 v3 = g_h1s[(size_t)s3 * (F1 / 4) + lane];
            acc.x += (v0.x + v1.x) + (v2.x + v3.x);
            acc.y += (v0.y + v1.y) + (v2.y + v3.y);
            acc.z += (v0.z + v1.z) + (v2.z + v3.z);
            acc.w += (v0.w + v1.w) + (v2.w + v3.w);
        }
        for (; i < e; i++) {
            int src = g_csr[i];
            float4 v = g_h1s[(size_t)src * (F1 / 4) + lane];
            acc.x += v.x; acc.y += v.y; acc.z += v.z; acc.w += v.w;
        }
        float dn = g_dinv[n];
        float4 o;
        o.x = fmaxf(fmaf(dn, acc.x, bx), 0.f);
        o.y = fmaxf(fmaf(dn, acc.y, by), 0.f);
        o.z = fmaxf(fmaf(dn, acc.z, bz), 0.f);
        o.w = fmaxf(fmaf(dn, acc.w, bw), 0.f);
        g_hidden[(size_t)n * (F1 / 4) + lane] = o;
    }
}

// Register-tiled GEMM2 over node range [lo, hi): h2s = (hidden @ W2) * dinv.
// lo is a multiple of 32 (chunking guarantees), tiles don't straddle chunks.
__global__ void __launch_bounds__(256) k_gemm2(const float* __restrict__ W2,
                                               int lo, int hi, int N) {
    __shared__ float4 W4s[F1][16];   // 32KB: W2[k][4*f4 .. +3]
    __shared__ float  xs[32][F1];    // 16KB
    int tid = threadIdx.x;
    for (int idx = tid; idx < F1 * 16; idx += 256) {
        int k = idx >> 4, f4 = idx & 15;
        W4s[k][f4] = *(const float4*)(W2 + k * F2 + 4 * f4);
    }
    int nd = tid >> 4;
    int f4 = tid & 15;
    const float* hidden = (const float*)g_hidden;
    int t0 = lo >> 5;
    int t1 = (hi + 31) >> 5;
    for (int t = t0 + blockIdx.x; t < t1; t += gridDim.x) {
        int base = t << 5;
        __syncthreads();
        for (int idx = tid; idx < 32 * (F1 / 4); idx += 256) {
            int r = idx >> 5, c4 = idx & 31;
            int nn = base + r;
            float4 v = (nn < N) ? *(const float4*)(hidden + (size_t)nn * F1 + 4 * c4)
                                : make_float4(0.f, 0.f, 0.f, 0.f);
            *(float4*)&xs[r][4 * c4] = v;
        }
        __syncthreads();
        float4 a0 = make_float4(0.f, 0.f, 0.f, 0.f);
        float4 a1 = make_float4(0.f, 0.f, 0.f, 0.f);
        #pragma unroll 4
        for (int k = 0; k < F1; k++) {
            float4 w = W4s[k][f4];
            float xa = xs[nd][k];
            float xb = xs[nd + 16][k];
            a0.x = fmaf(xa, w.x, a0.x); a0.y = fmaf(xa, w.y, a0.y);
            a0.z = fmaf(xa, w.z, a0.z); a0.w = fmaf(xa, w.w, a0.w);
            a1.x = fmaf(xb, w.x, a1.x); a1.y = fmaf(xb, w.y, a1.y);
            a1.z = fmaf(xb, w.z, a1.z); a1.w = fmaf(xb, w.w, a1.w);
        }
        int na = base + nd, nb = base + nd + 16;
        if (na < N) {
            float d = g_dinv[na];
            g_h2s[(size_t)na * (F2 / 4) + f4] =
                make_float4(a0.x * d, a0.y * d, a0.z * d, a0.w * d);
        }
        if (nb < N) {
            float d = g_dinv[nb];
            g_h2s[(size_t)nb * (F2 / 4) + f4] =
                make_float4(a1.x * d, a1.y * d, a1.z * d, a1.w * d);
        }
    }
}

// Aggregate layer 2: warp per node, 4-way unrolled gather, fused bias.
__global__ void __launch_bounds__(256) k_agg2(const float* __restrict__ b2,
                                              float* __restrict__ out, int N) {
    int lane  = threadIdx.x & 31;
    int warp  = (blockIdx.x * blockDim.x + threadIdx.x) >> 5;
    int nwarp = (gridDim.x * blockDim.x) >> 5;
    float bx = b2[2 * lane + 0], by = b2[2 * lane + 1];
    const float2* h2s = (const float2*)g_h2s;
    for (int n = warp; n < N; n += nwarp) {
        float2 acc = h2s[(size_t)n * (F2 / 2) + lane];   // self loop
        int s = g_rowstart[n], e = g_rowstart[n + 1];
        int i = s;
        for (; i + 4 <= e; i += 4) {
            int s0 = g_csr[i], s1 = g_csr[i + 1], s2 = g_csr[i + 2], s3 = g_csr[i + 3];
            float2 v0 = h2s[(size_t)s0 * (F2 / 2) + lane];
            float2 v1 = h2s[(size_t)s1 * (F2 / 2) + lane];
            float2 v2 = h2s[(size_t)s2 * (F2 / 2) + lane];
            float2 v3 = h2s[(size_t)s3 * (F2 / 2) + lane];
            acc.x += (v0.x + v1.x) + (v2.x + v3.x);
            acc.y += (v0.y + v1.y) + (v2.y + v3.y);
        }
        for (; i < e; i++) {
            int src = g_csr[i];
            float2 v = h2s[(size_t)src * (F2 / 2) + lane];
            acc.x += v.x; acc.y += v.y;
        }
        float dn = g_dinv[n];
        out[(size_t)n * F2 + 2 * lane + 0] = fmaf(dn, acc.x, bx);
        out[(size_t)n * F2 + 2 * lane + 1] = fmaf(dn, acc.y, by);
    }
}

// ---------------- launcher ---------------------------------------------------

static cudaStream_t aux_stream() {
    static cudaStream_t s = nullptr;
    if (!s) cudaStreamCreateWithFlags(&s, cudaStreamNonBlocking);
    return s;
}
#define NEVT (2 + 2 * NCHUNK)
static cudaEvent_t aux_event(int which) {
    static cudaEvent_t ev[NEVT] = {};
    if (!ev[which]) cudaEventCreateWithFlags(&ev[which], cudaEventDisableTiming);
    return ev[which];
}

extern "C" void kernel_launch(void* const* d_in, const int* in_sizes, int n_in,
                              void* d_out, int out_size) {
    const float* x  = (const float*)d_in[0];
    const void*  ei = d_in[1];                 // int32 or int64 — probed on device
    // d_in[2] = edge_weight (unused: reference overwrites with ones)
    const float* W1 = (const float*)d_in[3];
    const float* b1 = (const float*)d_in[4];
    const float* W2 = (const float*)d_in[5];
    const float* b2 = (const float*)d_in[6];
    float*       out = (float*)d_out;

    int N = in_sizes[0] / F1;
    int E = in_sizes[1] / 2;
    if (N > NMAX) N = NMAX;
    if (E > EMAX) E = EMAX;
    int nb = (N + SCAN_B - 1) / SCAN_B;

    cudaStream_t s2 = aux_stream();
    cudaEvent_t evFork = aux_event(0);
    cudaEvent_t evJoin = aux_event(1);

    // --- serial prefix: dtype probe + zero counts, degree counts, dinv ---
    k_init<<<(N + 255) / 256, 256>>>((const int*)ei, N);
    k_count<<<(E + 255) / 256, 256>>>(ei, E, N);
    k_dinv<<<(N + 255) / 256, 256>>>(N);

    // --- fork: GEMM1 (needs only dinv) runs concurrent with CSR build ---
    cudaEventRecord(evFork, 0);
    cudaStreamWaitEvent(s2, evFork, 0);
    dim3 g1(592, 2);
    k_gemm1<<<g1, 256, 0, s2>>>(x, W1, N);
    cudaEventRecord(evJoin, s2);

    k_scan_partial<<<nb, SCAN_B>>>(N);
    k_scan_blk<<<1, 256>>>(nb, N);
    k_scan_apply<<<nb, SCAN_B>>>(N);
    k_fill<<<(E + 255) / 256, 256>>>(ei, E, N);

    // --- join: aggregation needs both CSR and h1s ---
    cudaStreamWaitEvent(0, evJoin, 0);

    // --- pipelined agg1 -> gemm2 over NCHUNK node ranges ---
    int chunk = (((N + NCHUNK - 1) / NCHUNK) + 31) & ~31;   // multiple of 32
    for (int c = 0; c < NCHUNK; c++) {
        int lo = c * chunk;
        int hi = lo + chunk; if (hi > N) hi = N;
        if (lo >= hi) continue;
        cudaEvent_t evA = aux_event(2 + c);
        cudaEvent_t evG = aux_event(2 + NCHUNK + c);
        k_agg1<<<((hi - lo) + 7) / 8, 256>>>(b1, lo, hi);
        cudaEventRecord(evA, 0);
        cudaStreamWaitEvent(s2, evA, 0);
        k_gemm2<<<296, 256, 0, s2>>>(W2, lo, hi, N);
        cudaEventRecord(evG, s2);
    }
    for (int c = 0; c < NCHUNK; c++) {
        int lo = c * chunk;
        if (lo >= N) continue;
        cudaStreamWaitEvent(0, aux_event(2 + NCHUNK + c), 0);
    }
    k_agg2<<<(N + 7) / 8, 256>>>(b2, out, N);
}

// round 12
// speedup vs baseline: 1.2651x; 1.2651x over previous
#include <cuda_runtime.h>
#include <cuda_bf16.h>
#include <math.h>

// Problem constants (shapes fixed by the dataset)
#define NMAX  100000
#define EMAX  1600000
#define F1    128
#define F2    64
#define SCAN_B 512
#define NBMAX ((NMAX + SCAN_B - 1) / SCAN_B)   // 196

// ---------------- scratch (static device globals; no allocation allowed) ----
__device__ int    g_is64;                 // 1 if edge_index is int64, else int32
__device__ int    g_cnt[NMAX];
__device__ int    g_bsum[NBMAX];
__device__ int    g_boff[NBMAX];
__device__ int    g_rowstart[NMAX + 1];
__device__ int    g_cursor[NMAX];
__device__ float  g_dinv[NMAX];
__device__ int    g_csr[EMAX];
__device__ float4 g_h1s[(size_t)NMAX * F1 / 4];     // (x @ W1) * dinv[row]
__device__ float4 g_hidden[(size_t)NMAX * F1 / 4];  // relu(dinv*(sum)+b1)
__device__ float4 g_h2s[(size_t)NMAX * F2 / 4];     // (hidden @ W2) * dinv[row]

// ---------------- build kernels ---------------------------------------------

// Zero degree counts; thread 0 also probes edge_index dtype
// (int64 values < 2^31 have zero high words).
__global__ void k_init(const int* __restrict__ ei_raw, int N) {
    int i = blockIdx.x * blockDim.x + threadIdx.x;
    if (i < N) g_cnt[i] = 0;
    if (i == 0) {
        int any = 0;
        for (int j = 0; j < 64; j++) any |= ei_raw[2 * j + 1];
        g_is64 = (any == 0) ? 1 : 0;
    }
}

// Decode edge target (int32 or int64 per flag), validate, count in-degree.
__global__ void k_count(const void* __restrict__ ei_raw, int E, int N) {
    int e = blockIdx.x * blockDim.x + threadIdx.x;
    if (e >= E) return;
    int c;
    if (g_is64) {
        const long long* ei = (const long long*)ei_raw;
        c = (int)ei[(size_t)E + e];
    } else {
        const int* ei = (const int*)ei_raw;
        c = ei[(size_t)E + e];
    }
    if ((unsigned)c < (unsigned)N) atomicAdd(&g_cnt[c], 1);
}

// dinv depends only on counts — computed early so GEMM1 can fork off here.
__global__ void k_dinv(int N) {
    int i = blockIdx.x * blockDim.x + threadIdx.x;
    if (i < N) g_dinv[i] = rsqrtf((float)(g_cnt[i] + 1));   // +1 self loop
}

// Phase 1: per-block sums of counts.
__global__ void __launch_bounds__(SCAN_B) k_scan_partial(int N) {
    __shared__ int red[SCAN_B / 32];
    int b = blockIdx.x, tid = threadIdx.x;
    int i = b * SCAN_B + tid;
    int v = (i < N) ? g_cnt[i] : 0;
    for (int o = 16; o > 0; o >>= 1) v += __shfl_down_sync(0xffffffffu, v, o);
    if ((tid & 31) == 0) red[tid >> 5] = v;
    __syncthreads();
    if (tid < SCAN_B / 32) {
        int s = red[tid];
        for (int o = (SCAN_B / 64); o > 0; o >>= 1) s += __shfl_down_sync(0xffffu, s, o);
        if (tid == 0) g_bsum[b] = s;
    }
}

// Phase 2: single block scans block sums -> exclusive offsets; writes total.
__global__ void __launch_bounds__(256) k_scan_blk(int nb, int N) {
    __shared__ int sh[256];
    int tid = threadIdx.x;
    int v = (tid < nb) ? g_bsum[tid] : 0;
    sh[tid] = v;
    __syncthreads();
    for (int o = 1; o < 256; o <<= 1) {
        int t = (tid >= o) ? sh[tid - o] : 0;
        __syncthreads();
        sh[tid] += t;
        __syncthreads();
    }
    if (tid < nb) g_boff[tid] = sh[tid] - v;       // exclusive
    if (tid == 255) g_rowstart[N] = sh[255];       // total
}

// Phase 3: block-local exclusive scan + offset -> rowstart/cursor.
__global__ void __launch_bounds__(SCAN_B) k_scan_apply(int N) {
    __shared__ int sh[SCAN_B];
    int b = blockIdx.x, tid = threadIdx.x;
    int i = b * SCAN_B + tid;
    int v = (i < N) ? g_cnt[i] : 0;
    sh[tid] = v;
    __syncthreads();
    for (int o = 1; o < SCAN_B; o <<= 1) {
        int t = (tid >= o) ? sh[tid - o] : 0;
        __syncthreads();
        sh[tid] += t;
        __syncthreads();
    }
    if (i < N) {
        int base = g_boff[b] + sh[tid] - v;        // exclusive prefix
        g_rowstart[i] = base;
        g_cursor[i]   = base;
    }
}

// Fill CSR: decode edges directly (no staging), place source into target bucket.
__global__ void k_fill(const void* __restrict__ ei_raw, int E, int N) {
    int e = blockIdx.x * blockDim.x + threadIdx.x;
    if (e >= E) return;
    int r, c;
    if (g_is64) {
        const long long* ei = (const long long*)ei_raw;
        r = (int)ei[e];
        c = (int)ei[(size_t)E + e];
    } else {
        const int* ei = (const int*)ei_raw;
        r = ei[e];
        c = ei[(size_t)E + e];
    }
    if ((unsigned)r >= (unsigned)N || (unsigned)c >= (unsigned)N) return;
    int pos = atomicAdd(&g_cursor[c], 1);
    g_csr[pos] = r;
}

// ---------------- compute kernels -------------------------------------------

// GEMM inner tile shared by both layers:
// 128 threads; thread = (nd 0..7) x (f4 0..15); computes 4 nodes x 4 features.
// Per 4-k group: 4 x-register LDS.128 + 4 W LDS.128 feed 64 FFMAs.

// GEMM1: h1s[n, fh+4*f4..+3] = (x[n] @ W1[:, ...]) * dinv[n].
// Tile 32 nodes x 64 features (half of F1 by blockIdx.y). smem 48KB.
__global__ void __launch_bounds__(128) k_gemm1(const float* __restrict__ x,
                                               const float* __restrict__ W1, int N) {
    __shared__ float4 W4s[F1][16];   // 32KB: W1[k][fh + 4*f4 .. +3]
    __shared__ float  xs[32][F1];    // 16KB
    int tid = threadIdx.x;
    int fh = blockIdx.y * 64;
    for (int idx = tid; idx < F1 * 16; idx += 128) {
        int k = idx >> 4, f4 = idx & 15;
        W4s[k][f4] = *(const float4*)(W1 + k * F1 + fh + 4 * f4);
    }
    int nd = tid >> 4;      // 0..7
    int f4 = tid & 15;      // 0..15 -> features fh+4*f4..+3
    int fo = (fh >> 2) + f4;
    int ntiles = (N + 31) >> 5;
    for (int t = blockIdx.x; t < ntiles; t += gridDim.x) {
        int base = t << 5;
        __syncthreads();   // xs reuse (also covers initial W load)
        for (int idx = tid; idx < 32 * (F1 / 4); idx += 128) {
            int r = idx >> 5, c4 = idx & 31;
            int nn = base + r;
            float4 v = (nn < N) ? *(const float4*)(x + (size_t)nn * F1 + 4 * c4)
                                : make_float4(0.f, 0.f, 0.f, 0.f);
            *(float4*)&xs[r][4 * c4] = v;
        }
        __syncthreads();
        float4 a0 = make_float4(0.f,0.f,0.f,0.f), a1 = a0, a2 = a0, a3 = a0;
        #pragma unroll 8
        for (int k4 = 0; k4 < F1 / 4; k4++) {
            float4 x0 = *(const float4*)&xs[nd     ][4 * k4];
            float4 x1 = *(const float4*)&xs[nd +  8][4 * k4];
            float4 x2 = *(const float4*)&xs[nd + 16][4 * k4];
            float4 x3 = *(const float4*)&xs[nd + 24][4 * k4];
            #pragma unroll
            for (int kk = 0; kk < 4; kk++) {
                float4 w = W4s[4 * k4 + kk][f4];
                float e0 = (&x0.x)[kk], e1 = (&x1.x)[kk];
                float e2 = (&x2.x)[kk], e3 = (&x3.x)[kk];
                a0.x = fmaf(e0, w.x, a0.x); a0.y = fmaf(e0, w.y, a0.y);
                a0.z = fmaf(e0, w.z, a0.z); a0.w = fmaf(e0, w.w, a0.w);
                a1.x = fmaf(e1, w.x, a1.x); a1.y = fmaf(e1, w.y, a1.y);
                a1.z = fmaf(e1, w.z, a1.z); a1.w = fmaf(e1, w.w, a1.w);
                a2.x = fmaf(e2, w.x, a2.x); a2.y = fmaf(e2, w.y, a2.y);
                a2.z = fmaf(e2, w.z, a2.z); a2.w = fmaf(e2, w.w, a2.w);
                a3.x = fmaf(e3, w.x, a3.x); a3.y = fmaf(e3, w.y, a3.y);
                a3.z = fmaf(e3, w.z, a3.z); a3.w = fmaf(e3, w.w, a3.w);
            }
        }
        #pragma unroll
        for (int j = 0; j < 4; j++) {
            int n = base + nd + 8 * j;
            if (n < N) {
                float d = g_dinv[n];
                float4 a = (j == 0) ? a0 : (j == 1) ? a1 : (j == 2) ? a2 : a3;
                g_h1s[(size_t)n * (F1 / 4) + fo] =
                    make_float4(a.x * d, a.y * d, a.z * d, a.w * d);
            }
        }
    }
}

// Aggregate layer 1: warp per node, 4-way unrolled gather, fused relu+bias.
__global__ void __launch_bounds__(256) k_agg1(const float* __restrict__ b1, int N) {
    int lane  = threadIdx.x & 31;
    int warp  = (blockIdx.x * blockDim.x + threadIdx.x) >> 5;
    int nwarp = (gridDim.x * blockDim.x) >> 5;
    float bx = b1[4 * lane + 0], by = b1[4 * lane + 1];
    float bz = b1[4 * lane + 2], bw = b1[4 * lane + 3];
    for (int n = warp; n < N; n += nwarp) {
        float4 acc = g_h1s[(size_t)n * (F1 / 4) + lane];   // self loop
        int s = g_rowstart[n], e = g_rowstart[n + 1];
        int i = s;
        for (; i + 4 <= e; i += 4) {
            int s0 = g_csr[i], s1 = g_csr[i + 1], s2 = g_csr[i + 2], s3 = g_csr[i + 3];
            float4 v0 = g_h1s[(size_t)s0 * (F1 / 4) + lane];
            float4 v1 = g_h1s[(size_t)s1 * (F1 / 4) + lane];
            float4 v2 = g_h1s[(size_t)s2 * (F1 / 4) + lane];
            float4 v3 = g_h1s[(size_t)s3 * (F1 / 4) + lane];
            acc.x += (v0.x + v1.x) + (v2.x + v3.x);
            acc.y += (v0.y + v1.y) + (v2.y + v3.y);
            acc.z += (v0.z + v1.z) + (v2.z + v3.z);
            acc.w += (v0.w + v1.w) + (v2.w + v3.w);
        }
        for (; i < e; i++) {
            int src = g_csr[i];
            float4 v = g_h1s[(size_t)src * (F1 / 4) + lane];
            acc.x += v.x; acc.y += v.y; acc.z += v.z; acc.w += v.w;
        }
        float dn = g_dinv[n];
        float4 o;
        o.x = fmaxf(fmaf(dn, acc.x, bx), 0.f);
        o.y = fmaxf(fmaf(dn, acc.y, by), 0.f);
        o.z = fmaxf(fmaf(dn, acc.z, bz), 0.f);
        o.w = fmaxf(fmaf(dn, acc.w, bw), 0.f);
        g_hidden[(size_t)n * (F1 / 4) + lane] = o;
    }
}

// GEMM2: h2s[n] = (hidden[n] @ W2) * dinv[n]. Tile 32 nodes x 64 features.
__global__ void __launch_bounds__(128) k_gemm2(const float* __restrict__ W2, int N) {
    __shared__ float4 W4s[F1][16];   // 32KB: W2[k][4*f4 .. +3]
    __shared__ float  xs[32][F1];    // 16KB
    int tid = threadIdx.x;
    for (int idx = tid; idx < F1 * 16; idx += 128) {
        int k = idx >> 4, f4 = idx & 15;
        W4s[k][f4] = *(const float4*)(W2 + k * F2 + 4 * f4);
    }
    int nd = tid >> 4;
    int f4 = tid & 15;
    const float* hidden = (const float*)g_hidden;
    int ntiles = (N + 31) >> 5;
    for (int t = blockIdx.x; t < ntiles; t += gridDim.x) {
        int base = t << 5;
        __syncthreads();
        for (int idx = tid; idx < 32 * (F1 / 4); idx += 128) {
            int r = idx >> 5, c4 = idx & 31;
            int nn = base + r;
            float4 v = (nn < N) ? *(const float4*)(hidden + (size_t)nn * F1 + 4 * c4)
                                : make_float4(0.f, 0.f, 0.f, 0.f);
            *(float4*)&xs[r][4 * c4] = v;
        }
        __syncthreads();
        float4 a0 = make_float4(0.f,0.f,0.f,0.f), a1 = a0, a2 = a0, a3 = a0;
        #pragma unroll 8
        for (int k4 = 0; k4 < F1 / 4; k4++) {
            float4 x0 = *(const float4*)&xs[nd     ][4 * k4];
            float4 x1 = *(const float4*)&xs[nd +  8][4 * k4];
            float4 x2 = *(const float4*)&xs[nd + 16][4 * k4];
            float4 x3 = *(const float4*)&xs[nd + 24][4 * k4];
            #pragma unroll
            for (int kk = 0; kk < 4; kk++) {
                float4 w = W4s[4 * k4 + kk][f4];
                float e0 = (&x0.x)[kk], e1 = (&x1.x)[kk];
                float e2 = (&x2.x)[kk], e3 = (&x3.x)[kk];
                a0.x = fmaf(e0, w.x, a0.x); a0.y = fmaf(e0, w.y, a0.y);
                a0.z = fmaf(e0, w.z, a0.z); a0.w = fmaf(e0, w.w, a0.w);
                a1.x = fmaf(e1, w.x, a1.x); a1.y = fmaf(e1, w.y, a1.y);
                a1.z = fmaf(e1, w.z, a1.z); a1.w = fmaf(e1, w.w, a1.w);
                a2.x = fmaf(e2, w.x, a2.x); a2.y = fmaf(e2, w.y, a2.y);
                a2.z = fmaf(e2, w.z, a2.z); a2.w = fmaf(e2, w.w, a2.w);
                a3.x = fmaf(e3, w.x, a3.x); a3.y = fmaf(e3, w.y, a3.y);
                a3.z = fmaf(e3, w.z, a3.z); a3.w = fmaf(e3, w.w, a3.w);
            }
        }
        #pragma unroll
        for (int j = 0; j < 4; j++) {
            int n = base + nd + 8 * j;
            if (n < N) {
                float d = g_dinv[n];
                float4 a = (j == 0) ? a0 : (j == 1) ? a1 : (j == 2) ? a2 : a3;
                g_h2s[(size_t)n * (F2 / 4) + f4] =
                    make_float4(a.x * d, a.y * d, a.z * d, a.w * d);
            }
        }
    }
}

// Aggregate layer 2: warp per node, 4-way unrolled gather, fused bias.
__global__ void __launch_bounds__(256) k_agg2(const float* __restrict__ b2,
                                              float* __restrict__ out, int N) {
    int lane  = threadIdx.x & 31;
    int warp  = (blockIdx.x * blockDim.x + threadIdx.x) >> 5;
    int nwarp = (gridDim.x * blockDim.x) >> 5;
    float bx = b2[2 * lane + 0], by = b2[2 * lane + 1];
    const float2* h2s = (const float2*)g_h2s;
    for (int n = warp; n < N; n += nwarp) {
        float2 acc = h2s[(size_t)n * (F2 / 2) + lane];   // self loop
        int s = g_rowstart[n], e = g_rowstart[n + 1];
        int i = s;
        for (; i + 4 <= e; i += 4) {
            int s0 = g_csr[i], s1 = g_csr[i + 1], s2 = g_csr[i + 2], s3 = g_csr[i + 3];
            float2 v0 = h2s[(size_t)s0 * (F2 / 2) + lane];
            float2 v1 = h2s[(size_t)s1 * (F2 / 2) + lane];
            float2 v2 = h2s[(size_t)s2 * (F2 / 2) + lane];
            float2 v3 = h2s[(size_t)s3 * (F2 / 2) + lane];
            acc.x += (v0.x + v1.x) + (v2.x + v3.x);
            acc.y += (v0.y + v1.y) + (v2.y + v3.y);
        }
        for (; i < e; i++) {
            int src = g_csr[i];
            float2 v = h2s[(size_t)src * (F2 / 2) + lane];
            acc.x += v.x; acc.y += v.y;
        }
        float dn = g_dinv[n];
        out[(size_t)n * F2 + 2 * lane + 0] = fmaf(dn, acc.x, bx);
        out[(size_t)n * F2 + 2 * lane + 1] = fmaf(dn, acc.y, by);
    }
}

// ---------------- launcher ---------------------------------------------------

static cudaStream_t aux_stream() {
    static cudaStream_t s = nullptr;
    if (!s) cudaStreamCreateWithFlags(&s, cudaStreamNonBlocking);
    return s;
}
static cudaEvent_t aux_event(int which) {
    static cudaEvent_t ev[2] = {nullptr, nullptr};
    if (!ev[which]) cudaEventCreateWithFlags(&ev[which], cudaEventDisableTiming);
    return ev[which];
}

extern "C" void kernel_launch(void* const* d_in, const int* in_sizes, int n_in,
                              void* d_out, int out_size) {
    const float* x  = (const float*)d_in[0];
    const void*  ei = d_in[1];                 // int32 or int64 — probed on device
    // d_in[2] = edge_weight (unused: reference overwrites with ones)
    const float* W1 = (const float*)d_in[3];
    const float* b1 = (const float*)d_in[4];
    const float* W2 = (const float*)d_in[5];
    const float* b2 = (const float*)d_in[6];
    float*       out = (float*)d_out;

    int N = in_sizes[0] / F1;
    int E = in_sizes[1] / 2;
    if (N > NMAX) N = NMAX;
    if (E > EMAX) E = EMAX;
    int nb = (N + SCAN_B - 1) / SCAN_B;

    cudaStream_t s2 = aux_stream();
    cudaEvent_t evFork = aux_event(0);
    cudaEvent_t evJoin = aux_event(1);

    // --- serial prefix: dtype probe + zero counts, degree counts, dinv ---
    k_init<<<(N + 255) / 256, 256>>>((const int*)ei, N);
    k_count<<<(E + 255) / 256, 256>>>(ei, E, N);
    k_dinv<<<(N + 255) / 256, 256>>>(N);

    // --- fork: GEMM1 (needs only dinv) runs concurrent with CSR build ---
    cudaEventRecord(evFork, 0);
    cudaStreamWaitEvent(s2, evFork, 0);
    dim3 g1(296, 2);   // 592 blocks = 4 per SM (48KB smem each)
    k_gemm1<<<g1, 128, 0, s2>>>(x, W1, N);
    cudaEventRecord(evJoin, s2);

    k_scan_partial<<<nb, SCAN_B>>>(N);
    k_scan_blk<<<1, 256>>>(nb, N);
    k_scan_apply<<<nb, SCAN_B>>>(N);
    k_fill<<<(E + 255) / 256, 256>>>(ei, E, N);

    // --- join: aggregation needs both CSR and h1s ---
    cudaStreamWaitEvent(0, evJoin, 0);
    k_agg1<<<(N + 7) / 8, 256>>>(b1, N);
    k_gemm2<<<592, 128>>>(W2, N);
    k_agg2<<<(N + 7) / 8, 256>>>(b2, out, N);
}

// round 13
// speedup vs baseline: 1.3861x; 1.0956x over previous
#include <cuda_runtime.h>
#include <cuda_bf16.h>
#include <cuda_fp16.h>
#include <math.h>

// Problem constants (shapes fixed by the dataset)
#define NMAX  100000
#define EMAX  1600000
#define F1    128
#define F2    64
#define SCAN_B 512
#define NBMAX ((NMAX + SCAN_B - 1) / SCAN_B)   // 196

// ---------------- scratch (static device globals; no allocation allowed) ----
__device__ int    g_is64;                 // 1 if edge_index is int64, else int32
__device__ int    g_cnt[NMAX];
__device__ int    g_bsum[NBMAX];
__device__ int    g_boff[NBMAX];
__device__ int    g_rowstart[NMAX + 1];
__device__ int    g_cursor[NMAX];
__device__ float  g_dinv[NMAX];
__device__ int    g_csr[EMAX];
// fp16 gather tensors (written once, gathered ~17x) — halves agg L2 traffic.
__device__ uint2  g_h1h[(size_t)NMAX * 32];         // h1s fp16: row = 32 uint2 (128 halves)
__device__ uint2  g_h2h[(size_t)NMAX * 16];         // h2s fp16: row = 16 uint2 (64 halves)
__device__ float4 g_hidden[(size_t)NMAX * F1 / 4];  // relu(dinv*(sum)+b1), fp32

// ---------------- build kernels ---------------------------------------------

// Zero degree counts; thread 0 also probes edge_index dtype
// (int64 values < 2^31 have zero high words).
__global__ void k_init(const int* __restrict__ ei_raw, int N) {
    int i = blockIdx.x * blockDim.x + threadIdx.x;
    if (i < N) g_cnt[i] = 0;
    if (i == 0) {
        int any = 0;
        for (int j = 0; j < 64; j++) any |= ei_raw[2 * j + 1];
        g_is64 = (any == 0) ? 1 : 0;
    }
}

// Decode edge target (int32 or int64 per flag), validate, count in-degree.
__global__ void k_count(const void* __restrict__ ei_raw, int E, int N) {
    int e = blockIdx.x * blockDim.x + threadIdx.x;
    if (e >= E) return;
    int c;
    if (g_is64) {
        const long long* ei = (const long long*)ei_raw;
        c = (int)ei[(size_t)E + e];
    } else {
        const int* ei = (const int*)ei_raw;
        c = ei[(size_t)E + e];
    }
    if ((unsigned)c < (unsigned)N) atomicAdd(&g_cnt[c], 1);
}

// dinv depends only on counts — computed early so GEMM1 can fork off here.
__global__ void k_dinv(int N) {
    int i = blockIdx.x * blockDim.x + threadIdx.x;
    if (i < N) g_dinv[i] = rsqrtf((float)(g_cnt[i] + 1));   // +1 self loop
}

// Phase 1: per-block sums of counts.
__global__ void __launch_bounds__(SCAN_B) k_scan_partial(int N) {
    __shared__ int red[SCAN_B / 32];
    int b = blockIdx.x, tid = threadIdx.x;
    int i = b * SCAN_B + tid;
    int v = (i < N) ? g_cnt[i] : 0;
    for (int o = 16; o > 0; o >>= 1) v += __shfl_down_sync(0xffffffffu, v, o);
    if ((tid & 31) == 0) red[tid >> 5] = v;
    __syncthreads();
    if (tid < SCAN_B / 32) {
        int s = red[tid];
        for (int o = (SCAN_B / 64); o > 0; o >>= 1) s += __shfl_down_sync(0xffffu, s, o);
        if (tid == 0) g_bsum[b] = s;
    }
}

// Phase 2: single block scans block sums -> exclusive offsets; writes total.
__global__ void __launch_bounds__(256) k_scan_blk(int nb, int N) {
    __shared__ int sh[256];
    int tid = threadIdx.x;
    int v = (tid < nb) ? g_bsum[tid] : 0;
    sh[tid] = v;
    __syncthreads();
    for (int o = 1; o < 256; o <<= 1) {
        int t = (tid >= o) ? sh[tid - o] : 0;
        __syncthreads();
        sh[tid] += t;
        __syncthreads();
    }
    if (tid < nb) g_boff[tid] = sh[tid] - v;       // exclusive
    if (tid == 255) g_rowstart[N] = sh[255];       // total
}

// Phase 3: block-local exclusive scan + offset -> rowstart/cursor.
__global__ void __launch_bounds__(SCAN_B) k_scan_apply(int N) {
    __shared__ int sh[SCAN_B];
    int b = blockIdx.x, tid = threadIdx.x;
    int i = b * SCAN_B + tid;
    int v = (i < N) ? g_cnt[i] : 0;
    sh[tid] = v;
    __syncthreads();
    for (int o = 1; o < SCAN_B; o <<= 1) {
        int t = (tid >= o) ? sh[tid - o] : 0;
        __syncthreads();
        sh[tid] += t;
        __syncthreads();
    }
    if (i < N) {
        int base = g_boff[b] + sh[tid] - v;        // exclusive prefix
        g_rowstart[i] = base;
        g_cursor[i]   = base;
    }
}

// Fill CSR: decode edges directly (no staging), place source into target bucket.
__global__ void k_fill(const void* __restrict__ ei_raw, int E, int N) {
    int e = blockIdx.x * blockDim.x + threadIdx.x;
    if (e >= E) return;
    int r, c;
    if (g_is64) {
        const long long* ei = (const long long*)ei_raw;
        r = (int)ei[e];
        c = (int)ei[(size_t)E + e];
    } else {
        const int* ei = (const int*)ei_raw;
        r = ei[e];
        c = ei[(size_t)E + e];
    }
    if ((unsigned)r >= (unsigned)N || (unsigned)c >= (unsigned)N) return;
    int pos = atomicAdd(&g_cursor[c], 1);
    g_csr[pos] = r;
}

// ---------------- helpers ----------------------------------------------------

__device__ __forceinline__ uint2 pack4h(float a, float b, float c, float d) {
    __half2 h01 = __floats2half2_rn(a, b);
    __half2 h23 = __floats2half2_rn(c, d);
    uint2 u;
    u.x = reinterpret_cast<unsigned&>(h01);
    u.y = reinterpret_cast<unsigned&>(h23);
    return u;
}

// ---------------- compute kernels -------------------------------------------

// GEMM1: h1h[n, fh+4*f4..+3] = fp16((x[n] @ W1[:, ...]) * dinv[n]).
// 128 threads; thread = (nd 0..7) x (f4 0..15); 4 nodes x 4 features each.
__global__ void __launch_bounds__(128) k_gemm1(const float* __restrict__ x,
                                               const float* __restrict__ W1, int N) {
    __shared__ float4 W4s[F1][16];   // 32KB: W1[k][fh + 4*f4 .. +3]
    __shared__ float  xs[32][F1];    // 16KB
    int tid = threadIdx.x;
    int fh = blockIdx.y * 64;
    for (int idx = tid; idx < F1 * 16; idx += 128) {
        int k = idx >> 4, f4 = idx & 15;
        W4s[k][f4] = *(const float4*)(W1 + k * F1 + fh + 4 * f4);
    }
    int nd = tid >> 4;      // 0..7
    int f4 = tid & 15;      // 0..15 -> features fh+4*f4..+3
    int fo = (fh >> 2) + f4;
    int ntiles = (N + 31) >> 5;
    for (int t = blockIdx.x; t < ntiles; t += gridDim.x) {
        int base = t << 5;
        __syncthreads();   // xs reuse (also covers initial W load)
        for (int idx = tid; idx < 32 * (F1 / 4); idx += 128) {
            int r = idx >> 5, c4 = idx & 31;
            int nn = base + r;
            float4 v = (nn < N) ? *(const float4*)(x + (size_t)nn * F1 + 4 * c4)
                                : make_float4(0.f, 0.f, 0.f, 0.f);
            *(float4*)&xs[r][4 * c4] = v;
        }
        __syncthreads();
        float4 a0 = make_float4(0.f,0.f,0.f,0.f), a1 = a0, a2 = a0, a3 = a0;
        #pragma unroll 8
        for (int k4 = 0; k4 < F1 / 4; k4++) {
            float4 x0 = *(const float4*)&xs[nd     ][4 * k4];
            float4 x1 = *(const float4*)&xs[nd +  8][4 * k4];
            float4 x2 = *(const float4*)&xs[nd + 16][4 * k4];
            float4 x3 = *(const float4*)&xs[nd + 24][4 * k4];
            #pragma unroll
            for (int kk = 0; kk < 4; kk++) {
                float4 w = W4s[4 * k4 + kk][f4];
                float e0 = (&x0.x)[kk], e1 = (&x1.x)[kk];
                float e2 = (&x2.x)[kk], e3 = (&x3.x)[kk];
                a0.x = fmaf(e0, w.x, a0.x); a0.y = fmaf(e0, w.y, a0.y);
                a0.z = fmaf(e0, w.z, a0.z); a0.w = fmaf(e0, w.w, a0.w);
                a1.x = fmaf(e1, w.x, a1.x); a1.y = fmaf(e1, w.y, a1.y);
                a1.z = fmaf(e1, w.z, a1.z); a1.w = fmaf(e1, w.w, a1.w);
                a2.x = fmaf(e2, w.x, a2.x); a2.y = fmaf(e2, w.y, a2.y);
                a2.z = fmaf(e2, w.z, a2.z); a2.w = fmaf(e2, w.w, a2.w);
                a3.x = fmaf(e3, w.x, a3.x); a3.y = fmaf(e3, w.y, a3.y);
                a3.z = fmaf(e3, w.z, a3.z); a3.w = fmaf(e3, w.w, a3.w);
            }
        }
        #pragma unroll
        for (int j = 0; j < 4; j++) {
            int n = base + nd + 8 * j;
            if (n < N) {
                float d = g_dinv[n];
                float4 a = (j == 0) ? a0 : (j == 1) ? a1 : (j == 2) ? a2 : a3;
                g_h1h[(size_t)n * 32 + fo] = pack4h(a.x * d, a.y * d, a.z * d, a.w * d);
            }
        }
    }
}

// Aggregate layer 1: warp per node, fp16 gather (8B/lane), fp32 accumulate.
__global__ void __launch_bounds__(256) k_agg1(const float* __restrict__ b1, int N) {
    int lane  = threadIdx.x & 31;
    int warp  = (blockIdx.x * blockDim.x + threadIdx.x) >> 5;
    int nwarp = (gridDim.x * blockDim.x) >> 5;
    float bx = b1[4 * lane + 0], by = b1[4 * lane + 1];
    float bz = b1[4 * lane + 2], bw = b1[4 * lane + 3];
    for (int n = warp; n < N; n += nwarp) {
        float4 acc = make_float4(0.f, 0.f, 0.f, 0.f);
        {   // self loop
            uint2 v = g_h1h[(size_t)n * 32 + lane];
            float2 f0 = __half22float2(reinterpret_cast<__half2&>(v.x));
            float2 f1 = __half22float2(reinterpret_cast<__half2&>(v.y));
            acc.x = f0.x; acc.y = f0.y; acc.z = f1.x; acc.w = f1.y;
        }
        int s = g_rowstart[n], e = g_rowstart[n + 1];
        int i = s;
        for (; i + 4 <= e; i += 4) {
            int s0 = g_csr[i], s1 = g_csr[i + 1], s2 = g_csr[i + 2], s3 = g_csr[i + 3];
            uint2 u0 = g_h1h[(size_t)s0 * 32 + lane];
            uint2 u1 = g_h1h[(size_t)s1 * 32 + lane];
            uint2 u2 = g_h1h[(size_t)s2 * 32 + lane];
            uint2 u3 = g_h1h[(size_t)s3 * 32 + lane];
            float2 p;
            p = __half22float2(reinterpret_cast<__half2&>(u0.x)); acc.x += p.x; acc.y += p.y;
            p = __half22float2(reinterpret_cast<__half2&>(u0.y)); acc.z += p.x; acc.w += p.y;
            p = __half22float2(reinterpret_cast<__half2&>(u1.x)); acc.x += p.x; acc.y += p.y;
            p = __half22float2(reinterpret_cast<__half2&>(u1.y)); acc.z += p.x; acc.w += p.y;
            p = __half22float2(reinterpret_cast<__half2&>(u2.x)); acc.x += p.x; acc.y += p.y;
            p = __half22float2(reinterpret_cast<__half2&>(u2.y)); acc.z += p.x; acc.w += p.y;
            p = __half22float2(reinterpret_cast<__half2&>(u3.x)); acc.x += p.x; acc.y += p.y;
            p = __half22float2(reinterpret_cast<__half2&>(u3.y)); acc.z += p.x; acc.w += p.y;
        }
        for (; i < e; i++) {
            int src = g_csr[i];
            uint2 u = g_h1h[(size_t)src * 32 + lane];
            float2 p;
            p = __half22float2(reinterpret_cast<__half2&>(u.x)); acc.x += p.x; acc.y += p.y;
            p = __half22float2(reinterpret_cast<__half2&>(u.y)); acc.z += p.x; acc.w += p.y;
        }
        float dn = g_dinv[n];
        float4 o;
        o.x = fmaxf(fmaf(dn, acc.x, bx), 0.f);
        o.y = fmaxf(fmaf(dn, acc.y, by), 0.f);
        o.z = fmaxf(fmaf(dn, acc.z, bz), 0.f);
        o.w = fmaxf(fmaf(dn, acc.w, bw), 0.f);
        g_hidden[(size_t)n * (F1 / 4) + lane] = o;
    }
}

// GEMM2: h2h[n] = fp16((hidden[n] @ W2) * dinv[n]). Tile 32 nodes x 64 features.
__global__ void __launch_bounds__(128) k_gemm2(const float* __restrict__ W2, int N) {
    __shared__ float4 W4s[F1][16];   // 32KB: W2[k][4*f4 .. +3]
    __shared__ float  xs[32][F1];    // 16KB
    int tid = threadIdx.x;
    for (int idx = tid; idx < F1 * 16; idx += 128) {
        int k = idx >> 4, f4 = idx & 15;
        W4s[k][f4] = *(const float4*)(W2 + k * F2 + 4 * f4);
    }
    int nd = tid >> 4;
    int f4 = tid & 15;
    const float* hidden = (const float*)g_hidden;
    int ntiles = (N + 31) >> 5;
    for (int t = blockIdx.x; t < ntiles; t += gridDim.x) {
        int base = t << 5;
        __syncthreads();
        for (int idx = tid; idx < 32 * (F1 / 4); idx += 128) {
            int r = idx >> 5, c4 = idx & 31;
            int nn = base + r;
            float4 v = (nn < N) ? *(const float4*)(hidden + (size_t)nn * F1 + 4 * c4)
                                : make_float4(0.f, 0.f, 0.f, 0.f);
            *(float4*)&xs[r][4 * c4] = v;
        }
        __syncthreads();
        float4 a0 = make_float4(0.f,0.f,0.f,0.f), a1 = a0, a2 = a0, a3 = a0;
        #pragma unroll 8
        for (int k4 = 0; k4 < F1 / 4; k4++) {
            float4 x0 = *(const float4*)&xs[nd     ][4 * k4];
            float4 x1 = *(const float4*)&xs[nd +  8][4 * k4];
            float4 x2 = *(const float4*)&xs[nd + 16][4 * k4];
            float4 x3 = *(const float4*)&xs[nd + 24][4 * k4];
            #pragma unroll
            for (int kk = 0; kk < 4; kk++) {
                float4 w = W4s[4 * k4 + kk][f4];
                float e0 = (&x0.x)[kk], e1 = (&x1.x)[kk];
                float e2 = (&x2.x)[kk], e3 = (&x3.x)[kk];
                a0.x = fmaf(e0, w.x, a0.x); a0.y = fmaf(e0, w.y, a0.y);
                a0.z = fmaf(e0, w.z, a0.z); a0.w = fmaf(e0, w.w, a0.w);
                a1.x = fmaf(e1, w.x, a1.x); a1.y = fmaf(e1, w.y, a1.y);
                a1.z = fmaf(e1, w.z, a1.z); a1.w = fmaf(e1, w.w, a1.w);
                a2.x = fmaf(e2, w.x, a2.x); a2.y = fmaf(e2, w.y, a2.y);
                a2.z = fmaf(e2, w.z, a2.z); a2.w = fmaf(e2, w.w, a2.w);
                a3.x = fmaf(e3, w.x, a3.x); a3.y = fmaf(e3, w.y, a3.y);
                a3.z = fmaf(e3, w.z, a3.z); a3.w = fmaf(e3, w.w, a3.w);
            }
        }
        #pragma unroll
        for (int j = 0; j < 4; j++) {
            int n = base + nd + 8 * j;
            if (n < N) {
                float d = g_dinv[n];
                float4 a = (j == 0) ? a0 : (j == 1) ? a1 : (j == 2) ? a2 : a3;
                g_h2h[(size_t)n * 16 + f4] = pack4h(a.x * d, a.y * d, a.z * d, a.w * d);
            }
        }
    }
}

// Aggregate layer 2: warp per node, fp16 gather (half2/lane), fp32 accumulate.
__global__ void __launch_bounds__(256) k_agg2(const float* __restrict__ b2,
                                              float* __restrict__ out, int N) {
    int lane  = threadIdx.x & 31;
    int warp  = (blockIdx.x * blockDim.x + threadIdx.x) >> 5;
    int nwarp = (gridDim.x * blockDim.x) >> 5;
    float bx = b2[2 * lane + 0], by = b2[2 * lane + 1];
    const __half2* h2p = (const __half2*)g_h2h;
    for (int n = warp; n < N; n += nwarp) {
        float2 acc;
        {   // self loop
            acc = __half22float2(h2p[(size_t)n * 32 + lane]);
        }
        int s = g_rowstart[n], e = g_rowstart[n + 1];
        int i = s;
        for (; i + 4 <= e; i += 4) {
            int s0 = g_csr[i], s1 = g_csr[i + 1], s2 = g_csr[i + 2], s3 = g_csr[i + 3];
            float2 v0 = __half22float2(h2p[(size_t)s0 * 32 + lane]);
            float2 v1 = __half22float2(h2p[(size_t)s1 * 32 + lane]);
            float2 v2 = __half22float2(h2p[(size_t)s2 * 32 + lane]);
            float2 v3 = __half22float2(h2p[(size_t)s3 * 32 + lane]);
            acc.x += (v0.x + v1.x) + (v2.x + v3.x);
            acc.y += (v0.y + v1.y) + (v2.y + v3.y);
        }
        for (; i < e; i++) {
            int src = g_csr[i];
            float2 v = __half22float2(h2p[(size_t)src * 32 + lane]);
            acc.x += v.x; acc.y += v.y;
        }
        float dn = g_dinv[n];
        out[(size_t)n * F2 + 2 * lane + 0] = fmaf(dn, acc.x, bx);
        out[(size_t)n * F2 + 2 * lane + 1] = fmaf(dn, acc.y, by);
    }
}

// ---------------- launcher ---------------------------------------------------

static cudaStream_t aux_stream() {
    static cudaStream_t s = nullptr;
    if (!s) cudaStreamCreateWithFlags(&s, cudaStreamNonBlocking);
    return s;
}
static cudaEvent_t aux_event(int which) {
    static cudaEvent_t ev[2] = {nullptr, nullptr};
    if (!ev[which]) cudaEventCreateWithFlags(&ev[which], cudaEventDisableTiming);
    return ev[which];
}

extern "C" void kernel_launch(void* const* d_in, const int* in_sizes, int n_in,
                              void* d_out, int out_size) {
    const float* x  = (const float*)d_in[0];
    const void*  ei = d_in[1];                 // int32 or int64 — probed on device
    // d_in[2] = edge_weight (unused: reference overwrites with ones)
    const float* W1 = (const float*)d_in[3];
    const float* b1 = (const float*)d_in[4];
    const float* W2 = (const float*)d_in[5];
    const float* b2 = (const float*)d_in[6];
    float*       out = (float*)d_out;

    int N = in_sizes[0] / F1;
    int E = in_sizes[1] / 2;
    if (N > NMAX) N = NMAX;
    if (E > EMAX) E = EMAX;
    int nb = (N + SCAN_B - 1) / SCAN_B;

    cudaStream_t s2 = aux_stream();
    cudaEvent_t evFork = aux_event(0);
    cudaEvent_t evJoin = aux_event(1);

    // --- serial prefix: dtype probe + zero counts, degree counts, dinv ---
    k_init<<<(N + 255) / 256, 256>>>((const int*)ei, N);
    k_count<<<(E + 255) / 256, 256>>>(ei, E, N);
    k_dinv<<<(N + 255) / 256, 256>>>(N);

    // --- fork: GEMM1 (needs only dinv) runs concurrent with CSR build ---
    cudaEventRecord(evFork, 0);
    cudaStreamWaitEvent(s2, evFork, 0);
    dim3 g1(296, 2);   // 592 blocks = 4 per SM (48KB smem each)
    k_gemm1<<<g1, 128, 0, s2>>>(x, W1, N);
    cudaEventRecord(evJoin, s2);

    k_scan_partial<<<nb, SCAN_B>>>(N);
    k_scan_blk<<<1, 256>>>(nb, N);
    k_scan_apply<<<nb, SCAN_B>>>(N);
    k_fill<<<(E + 255) / 256, 256>>>(ei, E, N);

    // --- join: aggregation needs both CSR and h1s ---
    cudaStreamWaitEvent(0, evJoin, 0);
    k_agg1<<<(N + 7) / 8, 256>>>(b1, N);
    k_gemm2<<<592, 128>>>(W2, N);
    k_agg2<<<(N + 7) / 8, 256>>>(b2, out, N);
}

// round 14
// speedup vs baseline: 1.4216x; 1.0256x over previous
#include <cuda_runtime.h>
#include <cuda_bf16.h>
#include <cuda_fp16.h>
#include <mma.h>
#include <math.h>

using namespace nvcuda;

// Problem constants (shapes fixed by the dataset)
#define NMAX  100000
#define EMAX  1600000
#define F1    128
#define F2    64
#define SCAN_B 512
#define NBMAX ((NMAX + SCAN_B - 1) / SCAN_B)   // 196
#define LDS_PAD 80                              // smem row stride (floats)

// ---------------- scratch (static device globals; no allocation allowed) ----
__device__ int    g_is64;                 // 1 if edge_index is int64, else int32
__device__ int    g_cnt[NMAX];
__device__ int    g_bsum[NBMAX];
__device__ int    g_boff[NBMAX];
__device__ int    g_rowstart[NMAX + 1];
__device__ int    g_cursor[NMAX];
__device__ float  g_dinv[NMAX];
__device__ int    g_csr[EMAX];
// fp16 gather tensors (written once, gathered ~17x) — halves agg L2 traffic.
__device__ uint2  g_h1h[(size_t)NMAX * 32];         // h1s fp16: row = 32 uint2 (128 halves)
__device__ uint2  g_h2h[(size_t)NMAX * 16];         // h2s fp16: row = 16 uint2 (64 halves)
__device__ float4 g_hidden[(size_t)NMAX * F1 / 4];  // relu(dinv*(sum)+b1), fp32

// ---------------- build kernels ---------------------------------------------

__global__ void k_init(const int* __restrict__ ei_raw, int N) {
    int i = blockIdx.x * blockDim.x + threadIdx.x;
    if (i < N) g_cnt[i] = 0;
    if (i == 0) {
        int any = 0;
        for (int j = 0; j < 64; j++) any |= ei_raw[2 * j + 1];
        g_is64 = (any == 0) ? 1 : 0;
    }
}

__global__ void k_count(const void* __restrict__ ei_raw, int E, int N) {
    int e = blockIdx.x * blockDim.x + threadIdx.x;
    if (e >= E) return;
    int c;
    if (g_is64) {
        const long long* ei = (const long long*)ei_raw;
        c = (int)ei[(size_t)E + e];
    } else {
        const int* ei = (const int*)ei_raw;
        c = ei[(size_t)E + e];
    }
    if ((unsigned)c < (unsigned)N) atomicAdd(&g_cnt[c], 1);
}

__global__ void k_dinv(int N) {
    int i = blockIdx.x * blockDim.x + threadIdx.x;
    if (i < N) g_dinv[i] = rsqrtf((float)(g_cnt[i] + 1));   // +1 self loop
}

__global__ void __launch_bounds__(SCAN_B) k_scan_partial(int N) {
    __shared__ int red[SCAN_B / 32];
    int b = blockIdx.x, tid = threadIdx.x;
    int i = b * SCAN_B + tid;
    int v = (i < N) ? g_cnt[i] : 0;
    for (int o = 16; o > 0; o >>= 1) v += __shfl_down_sync(0xffffffffu, v, o);
    if ((tid & 31) == 0) red[tid >> 5] = v;
    __syncthreads();
    if (tid < SCAN_B / 32) {
        int s = red[tid];
        for (int o = (SCAN_B / 64); o > 0; o >>= 1) s += __shfl_down_sync(0xffffu, s, o);
        if (tid == 0) g_bsum[b] = s;
    }
}

__global__ void __launch_bounds__(256) k_scan_blk(int nb, int N) {
    __shared__ int sh[256];
    int tid = threadIdx.x;
    int v = (tid < nb) ? g_bsum[tid] : 0;
    sh[tid] = v;
    __syncthreads();
    for (int o = 1; o < 256; o <<= 1) {
        int t = (tid >= o) ? sh[tid - o] : 0;
        __syncthreads();
        sh[tid] += t;
        __syncthreads();
    }
    if (tid < nb) g_boff[tid] = sh[tid] - v;       // exclusive
    if (tid == 255) g_rowstart[N] = sh[255];       // total
}

__global__ void __launch_bounds__(SCAN_B) k_scan_apply(int N) {
    __shared__ int sh[SCAN_B];
    int b = blockIdx.x, tid = threadIdx.x;
    int i = b * SCAN_B + tid;
    int v = (i < N) ? g_cnt[i] : 0;
    sh[tid] = v;
    __syncthreads();
    for (int o = 1; o < SCAN_B; o <<= 1) {
        int t = (tid >= o) ? sh[tid - o] : 0;
        __syncthreads();
        sh[tid] += t;
        __syncthreads();
    }
    if (i < N) {
        int base = g_boff[b] + sh[tid] - v;        // exclusive prefix
        g_rowstart[i] = base;
        g_cursor[i]   = base;
    }
}

__global__ void k_fill(const void* __restrict__ ei_raw, int E, int N) {
    int e = blockIdx.x * blockDim.x + threadIdx.x;
    if (e >= E) return;
    int r, c;
    if (g_is64) {
        const long long* ei = (const long long*)ei_raw;
        r = (int)ei[e];
        c = (int)ei[(size_t)E + e];
    } else {
        const int* ei = (const int*)ei_raw;
        r = ei[e];
        c = ei[(size_t)E + e];
    }
    if ((unsigned)r >= (unsigned)N || (unsigned)c >= (unsigned)N) return;
    int pos = atomicAdd(&g_cursor[c], 1);
    g_csr[pos] = r;
}

// ---------------- helpers ----------------------------------------------------

__device__ __forceinline__ uint2 pack4h(float a, float b, float c, float d) {
    __half2 h01 = __floats2half2_rn(a, b);
    __half2 h23 = __floats2half2_rn(c, d);
    uint2 u;
    u.x = reinterpret_cast<unsigned&>(h01);
    u.y = reinterpret_cast<unsigned&>(h23);
    return u;
}

// ---------------- tensor-core GEMMs (tf32 wmma, fp32 accumulate) -------------
//
// Tile: 64 nodes x 64 features, K=128 in two 64-chunks.
// A = (rows * dinv) as tf32 in smem [64][LDS_PAD]; B = W chunk tf32 [64][LDS_PAD].
// 256 threads = 8 warps; warp w computes a 16x32 strip (2 m16n16k8 frags).
// Epilogue: C staged back through the A buffer, scaled nothing (dinv folded), fp16 pack.

// GEMM1: g_h1h[n, fh..fh+63] = fp16((x[n]*dinv[n]) @ W1[:, fh..fh+63])
__global__ void __launch_bounds__(256) k_gemm1(const float* __restrict__ x,
                                               const float* __restrict__ W1, int N) {
    __shared__ float As[64][LDS_PAD];   // 20KB (A tile; reused for C in epilogue)
    __shared__ float Bs[64][LDS_PAD];   // 20KB (W chunk)
    int tid = threadIdx.x;
    int fh = blockIdx.y * 64;
    int base = blockIdx.x * 64;
    int wid = tid >> 5;
    int tm = (wid >> 1) * 16;          // warp tile row: 0,16,32,48
    int tn = (wid & 1) * 32;           // warp tile col: 0,32

    wmma::fragment<wmma::accumulator, 16, 16, 8, float> c0, c1;
    wmma::fill_fragment(c0, 0.f);
    wmma::fill_fragment(c1, 0.f);

    for (int ph = 0; ph < 2; ph++) {
        __syncthreads();   // previous phase consumers done
        // Fill A: 64 rows x 16 float4 (1024 slots / 256 thr = 4 each)
        for (int idx = tid; idx < 1024; idx += 256) {
            int r = idx >> 4, c4 = idx & 15;
            int n = base + r;
            float4 v = make_float4(0.f, 0.f, 0.f, 0.f);
            float d = 0.f;
            if (n < N) {
                v = *(const float4*)(x + (size_t)n * F1 + ph * 64 + 4 * c4);
                d = g_dinv[n];
            }
            As[r][4 * c4 + 0] = wmma::__float_to_tf32(v.x * d);
            As[r][4 * c4 + 1] = wmma::__float_to_tf32(v.y * d);
            As[r][4 * c4 + 2] = wmma::__float_to_tf32(v.z * d);
            As[r][4 * c4 + 3] = wmma::__float_to_tf32(v.w * d);
        }
        // Fill B: W1 rows ph*64..+63, cols fh..fh+63
        for (int idx = tid; idx < 1024; idx += 256) {
            int r = idx >> 4, c4 = idx & 15;
            float4 v = *(const float4*)(W1 + (size_t)(ph * 64 + r) * F1 + fh + 4 * c4);
            Bs[r][4 * c4 + 0] = wmma::__float_to_tf32(v.x);
            Bs[r][4 * c4 + 1] = wmma::__float_to_tf32(v.y);
            Bs[r][4 * c4 + 2] = wmma::__float_to_tf32(v.z);
            Bs[r][4 * c4 + 3] = wmma::__float_to_tf32(v.w);
        }
        __syncthreads();
        #pragma unroll
        for (int k8 = 0; k8 < 8; k8++) {
            wmma::fragment<wmma::matrix_a, 16, 16, 8, wmma::precision::tf32, wmma::row_major> a;
            wmma::fragment<wmma::matrix_b, 16, 16, 8, wmma::precision::tf32, wmma::row_major> b0, b1;
            wmma::load_matrix_sync(a, &As[tm][k8 * 8], LDS_PAD);
            wmma::load_matrix_sync(b0, &Bs[k8 * 8][tn], LDS_PAD);
            wmma::load_matrix_sync(b1, &Bs[k8 * 8][tn + 16], LDS_PAD);
            wmma::mma_sync(c0, a, b0, c0);
            wmma::mma_sync(c1, a, b1, c1);
        }
    }
    __syncthreads();   // all warps done reading As
    wmma::store_matrix_sync(&As[tm][tn], c0, LDS_PAD, wmma::mem_row_major);
    wmma::store_matrix_sync(&As[tm][tn + 16], c1, LDS_PAD, wmma::mem_row_major);
    __syncthreads();
    // Pack fp16: 64 rows x 16 uint2 = 1024 slots
    int fo = fh >> 2;
    for (int idx = tid; idx < 1024; idx += 256) {
        int r = idx >> 4, q = idx & 15;
        int n = base + r;
        if (n < N) {
            float4 v = *(const float4*)&As[r][4 * q];
            g_h1h[(size_t)n * 32 + fo + q] = pack4h(v.x, v.y, v.z, v.w);
        }
    }
}

// GEMM2: g_h2h[n] = fp16((hidden[n]*dinv[n]) @ W2)
__global__ void __launch_bounds__(256) k_gemm2(const float* __restrict__ W2, int N) {
    __shared__ float As[64][LDS_PAD];
    __shared__ float Bs[64][LDS_PAD];
    int tid = threadIdx.x;
    int base = blockIdx.x * 64;
    int wid = tid >> 5;
    int tm = (wid >> 1) * 16;
    int tn = (wid & 1) * 32;
    const float* hidden = (const float*)g_hidden;

    wmma::fragment<wmma::accumulator, 16, 16, 8, float> c0, c1;
    wmma::fill_fragment(c0, 0.f);
    wmma::fill_fragment(c1, 0.f);

    for (int ph = 0; ph < 2; ph++) {
        __syncthreads();
        for (int idx = tid; idx < 1024; idx += 256) {
            int r = idx >> 4, c4 = idx & 15;
            int n = base + r;
            float4 v = make_float4(0.f, 0.f, 0.f, 0.f);
            float d = 0.f;
            if (n < N) {
                v = *(const float4*)(hidden + (size_t)n * F1 + ph * 64 + 4 * c4);
                d = g_dinv[n];
            }
            As[r][4 * c4 + 0] = wmma::__float_to_tf32(v.x * d);
            As[r][4 * c4 + 1] = wmma::__float_to_tf32(v.y * d);
            As[r][4 * c4 + 2] = wmma::__float_to_tf32(v.z * d);
            As[r][4 * c4 + 3] = wmma::__float_to_tf32(v.w * d);
        }
        for (int idx = tid; idx < 1024; idx += 256) {
            int r = idx >> 4, c4 = idx & 15;
            float4 v = *(const float4*)(W2 + (size_t)(ph * 64 + r) * F2 + 4 * c4);
            Bs[r][4 * c4 + 0] = wmma::__float_to_tf32(v.x);
            Bs[r][4 * c4 + 1] = wmma::__float_to_tf32(v.y);
            Bs[r][4 * c4 + 2] = wmma::__float_to_tf32(v.z);
            Bs[r][4 * c4 + 3] = wmma::__float_to_tf32(v.w);
        }
        __syncthreads();
        #pragma unroll
        for (int k8 = 0; k8 < 8; k8++) {
            wmma::fragment<wmma::matrix_a, 16, 16, 8, wmma::precision::tf32, wmma::row_major> a;
            wmma::fragment<wmma::matrix_b, 16, 16, 8, wmma::precision::tf32, wmma::row_major> b0, b1;
            wmma::load_matrix_sync(a, &As[tm][k8 * 8], LDS_PAD);
            wmma::load_matrix_sync(b0, &Bs[k8 * 8][tn], LDS_PAD);
            wmma::load_matrix_sync(b1, &Bs[k8 * 8][tn + 16], LDS_PAD);
            wmma::mma_sync(c0, a, b0, c0);
            wmma::mma_sync(c1, a, b1, c1);
        }
    }
    __syncthreads();
    wmma::store_matrix_sync(&As[tm][tn], c0, LDS_PAD, wmma::mem_row_major);
    wmma::store_matrix_sync(&As[tm][tn + 16], c1, LDS_PAD, wmma::mem_row_major);
    __syncthreads();
    for (int idx = tid; idx < 1024; idx += 256) {
        int r = idx >> 4, q = idx & 15;
        int n = base + r;
        if (n < N) {
            float4 v = *(const float4*)&As[r][4 * q];
            g_h2h[(size_t)n * 16 + q] = pack4h(v.x, v.y, v.z, v.w);
        }
    }
}

// ---------------- aggregation kernels (unchanged from R12 winner) ------------

__global__ void __launch_bounds__(256) k_agg1(const float* __restrict__ b1, int N) {
    int lane  = threadIdx.x & 31;
    int warp  = (blockIdx.x * blockDim.x + threadIdx.x) >> 5;
    int nwarp = (gridDim.x * blockDim.x) >> 5;
    float bx = b1[4 * lane + 0], by = b1[4 * lane + 1];
    float bz = b1[4 * lane + 2], bw = b1[4 * lane + 3];
    for (int n = warp; n < N; n += nwarp) {
        float4 acc = make_float4(0.f, 0.f, 0.f, 0.f);
        {   // self loop
            uint2 v = g_h1h[(size_t)n * 32 + lane];
            float2 f0 = __half22float2(reinterpret_cast<__half2&>(v.x));
            float2 f1 = __half22float2(reinterpret_cast<__half2&>(v.y));
            acc.x = f0.x; acc.y = f0.y; acc.z = f1.x; acc.w = f1.y;
        }
        int s = g_rowstart[n], e = g_rowstart[n + 1];
        int i = s;
        for (; i + 4 <= e; i += 4) {
            int s0 = g_csr[i], s1 = g_csr[i + 1], s2 = g_csr[i + 2], s3 = g_csr[i + 3];
            uint2 u0 = g_h1h[(size_t)s0 * 32 + lane];
            uint2 u1 = g_h1h[(size_t)s1 * 32 + lane];
            uint2 u2 = g_h1h[(size_t)s2 * 32 + lane];
            uint2 u3 = g_h1h[(size_t)s3 * 32 + lane];
            float2 p;
            p = __half22float2(reinterpret_cast<__half2&>(u0.x)); acc.x += p.x; acc.y += p.y;
            p = __half22float2(reinterpret_cast<__half2&>(u0.y)); acc.z += p.x; acc.w += p.y;
            p = __half22float2(reinterpret_cast<__half2&>(u1.x)); acc.x += p.x; acc.y += p.y;
            p = __half22float2(reinterpret_cast<__half2&>(u1.y)); acc.z += p.x; acc.w += p.y;
            p = __half22float2(reinterpret_cast<__half2&>(u2.x)); acc.x += p.x; acc.y += p.y;
            p = __half22float2(reinterpret_cast<__half2&>(u2.y)); acc.z += p.x; acc.w += p.y;
            p = __half22float2(reinterpret_cast<__half2&>(u3.x)); acc.x += p.x; acc.y += p.y;
            p = __half22float2(reinterpret_cast<__half2&>(u3.y)); acc.z += p.x; acc.w += p.y;
        }
        for (; i < e; i++) {
            int src = g_csr[i];
            uint2 u = g_h1h[(size_t)src * 32 + lane];
            float2 p;
            p = __half22float2(reinterpret_cast<__half2&>(u.x)); acc.x += p.x; acc.y += p.y;
            p = __half22float2(reinterpret_cast<__half2&>(u.y)); acc.z += p.x; acc.w += p.y;
        }
        float dn = g_dinv[n];
        float4 o;
        o.x = fmaxf(fmaf(dn, acc.x, bx), 0.f);
        o.y = fmaxf(fmaf(dn, acc.y, by), 0.f);
        o.z = fmaxf(fmaf(dn, acc.z, bz), 0.f);
        o.w = fmaxf(fmaf(dn, acc.w, bw), 0.f);
        g_hidden[(size_t)n * (F1 / 4) + lane] = o;
    }
}

__global__ void __launch_bounds__(256) k_agg2(const float* __restrict__ b2,
                                              float* __restrict__ out, int N) {
    int lane  = threadIdx.x & 31;
    int warp  = (blockIdx.x * blockDim.x + threadIdx.x) >> 5;
    int nwarp = (gridDim.x * blockDim.x) >> 5;
    float bx = b2[2 * lane + 0], by = b2[2 * lane + 1];
    const __half2* h2p = (const __half2*)g_h2h;
    for (int n = warp; n < N; n += nwarp) {
        float2 acc;
        {   // self loop
            acc = __half22float2(h2p[(size_t)n * 32 + lane]);
        }
        int s = g_rowstart[n], e = g_rowstart[n + 1];
        int i = s;
        for (; i + 4 <= e; i += 4) {
            int s0 = g_csr[i], s1 = g_csr[i + 1], s2 = g_csr[i + 2], s3 = g_csr[i + 3];
            float2 v0 = __half22float2(h2p[(size_t)s0 * 32 + lane]);
            float2 v1 = __half22float2(h2p[(size_t)s1 * 32 + lane]);
            float2 v2 = __half22float2(h2p[(size_t)s2 * 32 + lane]);
            float2 v3 = __half22float2(h2p[(size_t)s3 * 32 + lane]);
            acc.x += (v0.x + v1.x) + (v2.x + v3.x);
            acc.y += (v0.y + v1.y) + (v2.y + v3.y);
        }
        for (; i < e; i++) {
            int src = g_csr[i];
            float2 v = __half22float2(h2p[(size_t)src * 32 + lane]);
            acc.x += v.x; acc.y += v.y;
        }
        float dn = g_dinv[n];
        out[(size_t)n * F2 + 2 * lane + 0] = fmaf(dn, acc.x, bx);
        out[(size_t)n * F2 + 2 * lane + 1] = fmaf(dn, acc.y, by);
    }
}

// ---------------- launcher ---------------------------------------------------

static cudaStream_t aux_stream() {
    static cudaStream_t s = nullptr;
    if (!s) cudaStreamCreateWithFlags(&s, cudaStreamNonBlocking);
    return s;
}
static cudaEvent_t aux_event(int which) {
    static cudaEvent_t ev[2] = {nullptr, nullptr};
    if (!ev[which]) cudaEventCreateWithFlags(&ev[which], cudaEventDisableTiming);
    return ev[which];
}

extern "C" void kernel_launch(void* const* d_in, const int* in_sizes, int n_in,
                              void* d_out, int out_size) {
    const float* x  = (const float*)d_in[0];
    const void*  ei = d_in[1];                 // int32 or int64 — probed on device
    // d_in[2] = edge_weight (unused: reference overwrites with ones)
    const float* W1 = (const float*)d_in[3];
    const float* b1 = (const float*)d_in[4];
    const float* W2 = (const float*)d_in[5];
    const float* b2 = (const float*)d_in[6];
    float*       out = (float*)d_out;

    int N = in_sizes[0] / F1;
    int E = in_sizes[1] / 2;
    if (N > NMAX) N = NMAX;
    if (E > EMAX) E = EMAX;
    int nb = (N + SCAN_B - 1) / SCAN_B;
    int ntile = (N + 63) / 64;

    cudaStream_t s2 = aux_stream();
    cudaEvent_t evFork = aux_event(0);
    cudaEvent_t evJoin = aux_event(1);

    // --- serial prefix: dtype probe + zero counts, degree counts, dinv ---
    k_init<<<(N + 255) / 256, 256>>>((const int*)ei, N);
    k_count<<<(E + 255) / 256, 256>>>(ei, E, N);
    k_dinv<<<(N + 255) / 256, 256>>>(N);

    // --- fork: GEMM1 (needs only dinv) runs concurrent with CSR build ---
    cudaEventRecord(evFork, 0);
    cudaStreamWaitEvent(s2, evFork, 0);
    dim3 g1(ntile, 2);
    k_gemm1<<<g1, 256, 0, s2>>>(x, W1, N);
    cudaEventRecord(evJoin, s2);

    k_scan_partial<<<nb, SCAN_B>>>(N);
    k_scan_blk<<<1, 256>>>(nb, N);
    k_scan_apply<<<nb, SCAN_B>>>(N);
    k_fill<<<(E + 255) / 256, 256>>>(ei, E, N);

    // --- join: aggregation needs both CSR and h1s ---
    cudaStreamWaitEvent(0, evJoin, 0);
    k_agg1<<<(N + 7) / 8, 256>>>(b1, N);
    k_gemm2<<<ntile, 256>>>(W2, N);
    k_agg2<<<(N + 7) / 8, 256>>>(b2, out, N);
}

// round 15
// speedup vs baseline: 1.9146x; 1.3468x over previous
#include <cuda_runtime.h>
#include <cuda_bf16.h>
#include <cuda_fp16.h>
#include <mma.h>
#include <math.h>

using namespace nvcuda;

// Problem constants (shapes fixed by the dataset)
#define NMAX  100000
#define EMAX  1600000
#define F1    128
#define F2    64
#define SCAN_B 512
#define NBMAX ((NMAX + SCAN_B - 1) / SCAN_B)   // 196

// smem layout constants (halves)
#define A_STRIDE 136            // 64 rows x 136 halves (272B rows, odd*16B)
#define B_STRIDE 72             // 128 rows x 72 halves (144B rows, odd*16B)
#define C_STRIDE 68             // 64 rows x 68 floats (272B rows)
#define A_BYTES  (64 * A_STRIDE * 2)     // 17408
#define B_BYTES  (128 * B_STRIDE * 2)    // 18432
#define SMEM_BYTES (A_BYTES + B_BYTES)   // 35840 (also >= C: 64*68*4=17408)

// ---------------- scratch (static device globals; no allocation allowed) ----
__device__ int    g_is64;                 // 1 if edge_index is int64, else int32
__device__ int    g_cnt[NMAX];
__device__ int    g_bsum[NBMAX];
__device__ int    g_boff[NBMAX];
__device__ int    g_rowstart[NMAX + 1];
__device__ int    g_cursor[NMAX];
__device__ float  g_dinv[NMAX];
__device__ int    g_csr[EMAX];
// fp16 gather tensors (written once, gathered ~17x) — halves agg L2 traffic.
__device__ uint2  g_h1h[(size_t)NMAX * 32];         // h1s fp16: row = 32 uint2 (128 halves)
__device__ uint2  g_h2h[(size_t)NMAX * 16];         // h2s fp16: row = 16 uint2 (64 halves)
__device__ float4 g_hidden[(size_t)NMAX * F1 / 4];  // relu(dinv*(sum)+b1), fp32

// ---------------- build kernels ---------------------------------------------

__global__ void k_init(const int* __restrict__ ei_raw, int N) {
    int i = blockIdx.x * blockDim.x + threadIdx.x;
    if (i < N) g_cnt[i] = 0;
    if (i == 0) {
        int any = 0;
        for (int j = 0; j < 64; j++) any |= ei_raw[2 * j + 1];
        g_is64 = (any == 0) ? 1 : 0;
    }
}

__global__ void k_count(const void* __restrict__ ei_raw, int E, int N) {
    int e = blockIdx.x * blockDim.x + threadIdx.x;
    if (e >= E) return;
    int c;
    if (g_is64) {
        const long long* ei = (const long long*)ei_raw;
        c = (int)ei[(size_t)E + e];
    } else {
        const int* ei = (const int*)ei_raw;
        c = ei[(size_t)E + e];
    }
    if ((unsigned)c < (unsigned)N) atomicAdd(&g_cnt[c], 1);
}

__global__ void k_dinv(int N) {
    int i = blockIdx.x * blockDim.x + threadIdx.x;
    if (i < N) g_dinv[i] = rsqrtf((float)(g_cnt[i] + 1));   // +1 self loop
}

__global__ void __launch_bounds__(SCAN_B) k_scan_partial(int N) {
    __shared__ int red[SCAN_B / 32];
    int b = blockIdx.x, tid = threadIdx.x;
    int i = b * SCAN_B + tid;
    int v = (i < N) ? g_cnt[i] : 0;
    for (int o = 16; o > 0; o >>= 1) v += __shfl_down_sync(0xffffffffu, v, o);
    if ((tid & 31) == 0) red[tid >> 5] = v;
    __syncthreads();
    if (tid < SCAN_B / 32) {
        int s = red[tid];
        for (int o = (SCAN_B / 64); o > 0; o >>= 1) s += __shfl_down_sync(0xffffu, s, o);
        if (tid == 0) g_bsum[b] = s;
    }
}

__global__ void __launch_bounds__(256) k_scan_blk(int nb, int N) {
    __shared__ int sh[256];
    int tid = threadIdx.x;
    int v = (tid < nb) ? g_bsum[tid] : 0;
    sh[tid] = v;
    __syncthreads();
    for (int o = 1; o < 256; o <<= 1) {
        int t = (tid >= o) ? sh[tid - o] : 0;
        __syncthreads();
        sh[tid] += t;
        __syncthreads();
    }
    if (tid < nb) g_boff[tid] = sh[tid] - v;       // exclusive
    if (tid == 255) g_rowstart[N] = sh[255];       // total
}

__global__ void __launch_bounds__(SCAN_B) k_scan_apply(int N) {
    __shared__ int sh[SCAN_B];
    int b = blockIdx.x, tid = threadIdx.x;
    int i = b * SCAN_B + tid;
    int v = (i < N) ? g_cnt[i] : 0;
    sh[tid] = v;
    __syncthreads();
    for (int o = 1; o < SCAN_B; o <<= 1) {
        int t = (tid >= o) ? sh[tid - o] : 0;
        __syncthreads();
        sh[tid] += t;
        __syncthreads();
    }
    if (i < N) {
        int base = g_boff[b] + sh[tid] - v;        // exclusive prefix
        g_rowstart[i] = base;
        g_cursor[i]   = base;
    }
}

__global__ void k_fill(const void* __restrict__ ei_raw, int E, int N) {
    int e = blockIdx.x * blockDim.x + threadIdx.x;
    if (e >= E) return;
    int r, c;
    if (g_is64) {
        const long long* ei = (const long long*)ei_raw;
        r = (int)ei[e];
        c = (int)ei[(size_t)E + e];
    } else {
        const int* ei = (const int*)ei_raw;
        r = ei[e];
        c = ei[(size_t)E + e];
    }
    if ((unsigned)r >= (unsigned)N || (unsigned)c >= (unsigned)N) return;
    int pos = atomicAdd(&g_cursor[c], 1);
    g_csr[pos] = r;
}

// ---------------- helpers ----------------------------------------------------

__device__ __forceinline__ uint2 pack4h(float a, float b, float c, float d) {
    __half2 h01 = __floats2half2_rn(a, b);
    __half2 h23 = __floats2half2_rn(c, d);
    uint2 u;
    u.x = reinterpret_cast<unsigned&>(h01);
    u.y = reinterpret_cast<unsigned&>(h23);
    return u;
}

// ---------------- tensor-core GEMMs (fp16 m16n16k16, fp32 accumulate) --------
//
// fp16 mantissa == tf32 mantissa (10 bits); data is O(1) so no range risk.
// Tile: 64 nodes x 64 features, full K=128 staged once (no phase loop).
// smem arena aliased: [A half 64x136 | B half 128x72] -> C float 64x68.
// 256 threads = 8 warps; warp computes one 16x32 strip (2 m16n16k16 frags).

// GEMM1: g_h1h[n, fh..fh+63] = fp16((x[n]*dinv[n]) @ W1[:, fh..fh+63])
__global__ void __launch_bounds__(256) k_gemm1(const float* __restrict__ x,
                                               const float* __restrict__ W1, int N) {
    __shared__ __align__(16) char smem_raw[SMEM_BYTES];
    __half* As = (__half*)smem_raw;
    __half* Bs = (__half*)(smem_raw + A_BYTES);
    float*  Cs = (float*)smem_raw;
    int tid = threadIdx.x;
    int fh = blockIdx.y * 64;
    int base = blockIdx.x * 64;
    int wid = tid >> 5;
    int tm = (wid >> 1) * 16;          // warp tile row: 0,16,32,48
    int tn = (wid & 1) * 32;           // warp tile col: 0,32

    // Fill A: 64 rows x 32 float4-groups (4 halves each) = 2048 slots
    for (int idx = tid; idx < 2048; idx += 256) {
        int r = idx >> 5, c = idx & 31;
        int n = base + r;
        float4 v = make_float4(0.f, 0.f, 0.f, 0.f);
        float d = 0.f;
        if (n < N) {
            v = *(const float4*)(x + (size_t)n * F1 + 4 * c);
            d = g_dinv[n];
        }
        *(uint2*)&As[r * A_STRIDE + 4 * c] = pack4h(v.x * d, v.y * d, v.z * d, v.w * d);
    }
    // Fill B: 128 rows x 16 float4-groups = 2048 slots (W1 cols fh..fh+63)
    for (int idx = tid; idx < 2048; idx += 256) {
        int r = idx >> 4, c = idx & 15;
        float4 v = *(const float4*)(W1 + (size_t)r * F1 + fh + 4 * c);
        *(uint2*)&Bs[r * B_STRIDE + 4 * c] = pack4h(v.x, v.y, v.z, v.w);
    }
    __syncthreads();

    wmma::fragment<wmma::accumulator, 16, 16, 16, float> c0, c1;
    wmma::fill_fragment(c0, 0.f);
    wmma::fill_fragment(c1, 0.f);
    #pragma unroll
    for (int k = 0; k < 8; k++) {
        wmma::fragment<wmma::matrix_a, 16, 16, 16, __half, wmma::row_major> a;
        wmma::fragment<wmma::matrix_b, 16, 16, 16, __half, wmma::row_major> b0, b1;
        wmma::load_matrix_sync(a, &As[tm * A_STRIDE + k * 16], A_STRIDE);
        wmma::load_matrix_sync(b0, &Bs[(k * 16) * B_STRIDE + tn], B_STRIDE);
        wmma::load_matrix_sync(b1, &Bs[(k * 16) * B_STRIDE + tn + 16], B_STRIDE);
        wmma::mma_sync(c0, a, b0, c0);
        wmma::mma_sync(c1, a, b1, c1);
    }
    __syncthreads();   // done reading As/Bs; arena becomes C
    wmma::store_matrix_sync(&Cs[tm * C_STRIDE + tn], c0, C_STRIDE, wmma::mem_row_major);
    wmma::store_matrix_sync(&Cs[tm * C_STRIDE + tn + 16], c1, C_STRIDE, wmma::mem_row_major);
    __syncthreads();
    // Pack fp16: 64 rows x 16 uint2 = 1024 slots
    int fo = fh >> 2;
    for (int idx = tid; idx < 1024; idx += 256) {
        int r = idx >> 4, q = idx & 15;
        int n = base + r;
        if (n < N) {
            float4 v = *(const float4*)&Cs[r * C_STRIDE + 4 * q];
            g_h1h[(size_t)n * 32 + fo + q] = pack4h(v.x, v.y, v.z, v.w);
        }
    }
}

// GEMM2: g_h2h[n] = fp16((hidden[n]*dinv[n]) @ W2)
__global__ void __launch_bounds__(256) k_gemm2(const float* __restrict__ W2, int N) {
    __shared__ __align__(16) char smem_raw[SMEM_BYTES];
    __half* As = (__half*)smem_raw;
    __half* Bs = (__half*)(smem_raw + A_BYTES);
    float*  Cs = (float*)smem_raw;
    int tid = threadIdx.x;
    int base = blockIdx.x * 64;
    int wid = tid >> 5;
    int tm = (wid >> 1) * 16;
    int tn = (wid & 1) * 32;
    const float* hidden = (const float*)g_hidden;

    for (int idx = tid; idx < 2048; idx += 256) {
        int r = idx >> 5, c = idx & 31;
        int n = base + r;
        float4 v = make_float4(0.f, 0.f, 0.f, 0.f);
        float d = 0.f;
        if (n < N) {
            v = *(const float4*)(hidden + (size_t)n * F1 + 4 * c);
            d = g_dinv[n];
        }
        *(uint2*)&As[r * A_STRIDE + 4 * c] = pack4h(v.x * d, v.y * d, v.z * d, v.w * d);
    }
    for (int idx = tid; idx < 2048; idx += 256) {
        int r = idx >> 4, c = idx & 15;
        float4 v = *(const float4*)(W2 + (size_t)r * F2 + 4 * c);
        *(uint2*)&Bs[r * B_STRIDE + 4 * c] = pack4h(v.x, v.y, v.z, v.w);
    }
    __syncthreads();

    wmma::fragment<wmma::accumulator, 16, 16, 16, float> c0, c1;
    wmma::fill_fragment(c0, 0.f);
    wmma::fill_fragment(c1, 0.f);
    #pragma unroll
    for (int k = 0; k < 8; k++) {
        wmma::fragment<wmma::matrix_a, 16, 16, 16, __half, wmma::row_major> a;
        wmma::fragment<wmma::matrix_b, 16, 16, 16, __half, wmma::row_major> b0, b1;
        wmma::load_matrix_sync(a, &As[tm * A_STRIDE + k * 16], A_STRIDE);
        wmma::load_matrix_sync(b0, &Bs[(k * 16) * B_STRIDE + tn], B_STRIDE);
        wmma::load_matrix_sync(b1, &Bs[(k * 16) * B_STRIDE + tn + 16], B_STRIDE);
        wmma::mma_sync(c0, a, b0, c0);
        wmma::mma_sync(c1, a, b1, c1);
    }
    __syncthreads();
    wmma::store_matrix_sync(&Cs[tm * C_STRIDE + tn], c0, C_STRIDE, wmma::mem_row_major);
    wmma::store_matrix_sync(&Cs[tm * C_STRIDE + tn + 16], c1, C_STRIDE, wmma::mem_row_major);
    __syncthreads();
    for (int idx = tid; idx < 1024; idx += 256) {
        int r = idx >> 4, q = idx & 15;
        int n = base + r;
        if (n < N) {
            float4 v = *(const float4*)&Cs[r * C_STRIDE + 4 * q];
            g_h2h[(size_t)n * 16 + q] = pack4h(v.x, v.y, v.z, v.w);
        }
    }
}

// ---------------- aggregation kernels (unchanged from R12 winner) ------------

__global__ void __launch_bounds__(256) k_agg1(const float* __restrict__ b1, int N) {
    int lane  = threadIdx.x & 31;
    int warp  = (blockIdx.x * blockDim.x + threadIdx.x) >> 5;
    int nwarp = (gridDim.x * blockDim.x) >> 5;
    float bx = b1[4 * lane + 0], by = b1[4 * lane + 1];
    float bz = b1[4 * lane + 2], bw = b1[4 * lane + 3];
    for (int n = warp; n < N; n += nwarp) {
        float4 acc = make_float4(0.f, 0.f, 0.f, 0.f);
        {   // self loop
            uint2 v = g_h1h[(size_t)n * 32 + lane];
            float2 f0 = __half22float2(reinterpret_cast<__half2&>(v.x));
            float2 f1 = __half22float2(reinterpret_cast<__half2&>(v.y));
            acc.x = f0.x; acc.y = f0.y; acc.z = f1.x; acc.w = f1.y;
        }
        int s = g_rowstart[n], e = g_rowstart[n + 1];
        int i = s;
        for (; i + 4 <= e; i += 4) {
            int s0 = g_csr[i], s1 = g_csr[i + 1], s2 = g_csr[i + 2], s3 = g_csr[i + 3];
            uint2 u0 = g_h1h[(size_t)s0 * 32 + lane];
            uint2 u1 = g_h1h[(size_t)s1 * 32 + lane];
            uint2 u2 = g_h1h[(size_t)s2 * 32 + lane];
            uint2 u3 = g_h1h[(size_t)s3 * 32 + lane];
            float2 p;
            p = __half22float2(reinterpret_cast<__half2&>(u0.x)); acc.x += p.x; acc.y += p.y;
            p = __half22float2(reinterpret_cast<__half2&>(u0.y)); acc.z += p.x; acc.w += p.y;
            p = __half22float2(reinterpret_cast<__half2&>(u1.x)); acc.x += p.x; acc.y += p.y;
            p = __half22float2(reinterpret_cast<__half2&>(u1.y)); acc.z += p.x; acc.w += p.y;
            p = __half22float2(reinterpret_cast<__half2&>(u2.x)); acc.x += p.x; acc.y += p.y;
            p = __half22float2(reinterpret_cast<__half2&>(u2.y)); acc.z += p.x; acc.w += p.y;
            p = __half22float2(reinterpret_cast<__half2&>(u3.x)); acc.x += p.x; acc.y += p.y;
            p = __half22float2(reinterpret_cast<__half2&>(u3.y)); acc.z += p.x; acc.w += p.y;
        }
        for (; i < e; i++) {
            int src = g_csr[i];
            uint2 u = g_h1h[(size_t)src * 32 + lane];
            float2 p;
            p = __half22float2(reinterpret_cast<__half2&>(u.x)); acc.x += p.x; acc.y += p.y;
            p = __half22float2(reinterpret_cast<__half2&>(u.y)); acc.z += p.x; acc.w += p.y;
        }
        float dn = g_dinv[n];
        float4 o;
        o.x = fmaxf(fmaf(dn, acc.x, bx), 0.f);
        o.y = fmaxf(fmaf(dn, acc.y, by), 0.f);
        o.z = fmaxf(fmaf(dn, acc.z, bz), 0.f);
        o.w = fmaxf(fmaf(dn, acc.w, bw), 0.f);
        g_hidden[(size_t)n * (F1 / 4) + lane] = o;
    }
}

__global__ void __launch_bounds__(256) k_agg2(const float* __restrict__ b2,
                                              float* __restrict__ out, int N) {
    int lane  = threadIdx.x & 31;
    int warp  = (blockIdx.x * blockDim.x + threadIdx.x) >> 5;
    int nwarp = (gridDim.x * blockDim.x) >> 5;
    float bx = b2[2 * lane + 0], by = b2[2 * lane + 1];
    const __half2* h2p = (const __half2*)g_h2h;
    for (int n = warp; n < N; n += nwarp) {
        float2 acc;
        {   // self loop
            acc = __half22float2(h2p[(size_t)n * 32 + lane]);
        }
        int s = g_rowstart[n], e = g_rowstart[n + 1];
        int i = s;
        for (; i + 4 <= e; i += 4) {
            int s0 = g_csr[i], s1 = g_csr[i + 1], s2 = g_csr[i + 2], s3 = g_csr[i + 3];
            float2 v0 = __half22float2(h2p[(size_t)s0 * 32 + lane]);
            float2 v1 = __half22float2(h2p[(size_t)s1 * 32 + lane]);
            float2 v2 = __half22float2(h2p[(size_t)s2 * 32 + lane]);
            float2 v3 = __half22float2(h2p[(size_t)s3 * 32 + lane]);
            acc.x += (v0.x + v1.x) + (v2.x + v3.x);
            acc.y += (v0.y + v1.y) + (v2.y + v3.y);
        }
        for (; i < e; i++) {
            int src = g_csr[i];
            float2 v = __half22float2(h2p[(size_t)src * 32 + lane]);
            acc.x += v.x; acc.y += v.y;
        }
        float dn = g_dinv[n];
        out[(size_t)n * F2 + 2 * lane + 0] = fmaf(dn, acc.x, bx);
        out[(size_t)n * F2 + 2 * lane + 1] = fmaf(dn, acc.y, by);
    }
}

// ---------------- launcher ---------------------------------------------------

static cudaStream_t aux_stream() {
    static cudaStream_t s = nullptr;
    if (!s) cudaStreamCreateWithFlags(&s, cudaStreamNonBlocking);
    return s;
}
static cudaEvent_t aux_event(int which) {
    static cudaEvent_t ev[2] = {nullptr, nullptr};
    if (!ev[which]) cudaEventCreateWithFlags(&ev[which], cudaEventDisableTiming);
    return ev[which];
}

extern "C" void kernel_launch(void* const* d_in, const int* in_sizes, int n_in,
                              void* d_out, int out_size) {
    const float* x  = (const float*)d_in[0];
    const void*  ei = d_in[1];                 // int32 or int64 — probed on device
    // d_in[2] = edge_weight (unused: reference overwrites with ones)
    const float* W1 = (const float*)d_in[3];
    const float* b1 = (const float*)d_in[4];
    const float* W2 = (const float*)d_in[5];
    const float* b2 = (const float*)d_in[6];
    float*       out = (float*)d_out;

    int N = in_sizes[0] / F1;
    int E = in_sizes[1] / 2;
    if (N > NMAX) N = NMAX;
    if (E > EMAX) E = EMAX;
    int nb = (N + SCAN_B - 1) / SCAN_B;
    int ntile = (N + 63) / 64;

    cudaStream_t s2 = aux_stream();
    cudaEvent_t evFork = aux_event(0);
    cudaEvent_t evJoin = aux_event(1);

    // --- serial prefix: dtype probe + zero counts, degree counts, dinv ---
    k_init<<<(N + 255) / 256, 256>>>((const int*)ei, N);
    k_count<<<(E + 255) / 256, 256>>>(ei, E, N);
    k_dinv<<<(N + 255) / 256, 256>>>(N);

    // --- fork: GEMM1 (needs only dinv) runs concurrent with CSR build ---
    cudaEventRecord(evFork, 0);
    cudaStreamWaitEvent(s2, evFork, 0);
    dim3 g1(ntile, 2);
    k_gemm1<<<g1, 256, 0, s2>>>(x, W1, N);
    cudaEventRecord(evJoin, s2);

    k_scan_partial<<<nb, SCAN_B>>>(N);
    k_scan_blk<<<1, 256>>>(nb, N);
    k_scan_apply<<<nb, SCAN_B>>>(N);
    k_fill<<<(E + 255) / 256, 256>>>(ei, E, N);

    // --- join: aggregation needs both CSR and h1s ---
    cudaStreamWaitEvent(0, evJoin, 0);
    k_agg1<<<(N + 7) / 8, 256>>>(b1, N);
    k_gemm2<<<ntile, 256>>>(W2, N);
    k_agg2<<<(N + 7) / 8, 256>>>(b2, out, N);
}

// round 16
// speedup vs baseline: 2.0000x; 1.0446x over previous
#include <cuda_runtime.h>
#include <cuda_bf16.h>
#include <cuda_fp16.h>
#include <mma.h>
#include <math.h>

using namespace nvcuda;

// Problem constants (shapes fixed by the dataset)
#define NMAX  100000
#define EMAX  1600000
#define F1    128
#define F2    64
#define SCAN_B 512
#define NBMAX ((NMAX + SCAN_B - 1) / SCAN_B)   // 196

// smem layout constants (halves)
#define A_STRIDE 136            // 64 rows x 136 halves (272B rows, odd*16B)
#define B_STRIDE 72             // 128 rows x 72 halves (144B rows, odd*16B)
#define C_STRIDE 68             // 64 rows x 68 floats (272B rows)
#define A_BYTES  (64 * A_STRIDE * 2)     // 17408
#define B_BYTES  (128 * B_STRIDE * 2)    // 18432
#define SMEM_BYTES (A_BYTES + B_BYTES)   // 35840 (also >= C: 64*68*4=17408)

// ---------------- scratch (static device globals; no allocation allowed) ----
__device__ int    g_is64;                 // 1 if edge_index is int64, else int32
__device__ int    g_cnt[NMAX];
__device__ int    g_bsum[NBMAX];
__device__ int    g_boff[NBMAX];
__device__ int    g_rowstart[NMAX + 1];
__device__ int    g_cursor[NMAX];
__device__ float  g_dinv[NMAX];
__device__ int    g_csr[EMAX];
// fp16 tensors: gathered ~17x (h1h/h2h) or streamed twice (hidh).
__device__ uint2  g_h1h[(size_t)NMAX * 32];   // h1s fp16: row = 32 uint2 (128 halves)
__device__ uint2  g_h2h[(size_t)NMAX * 16];   // h2s fp16: row = 16 uint2 (64 halves)
__device__ uint2  g_hidh[(size_t)NMAX * 32];  // hidden fp16: row = 32 uint2

// ---------------- build kernels ---------------------------------------------

__global__ void k_init(const int* __restrict__ ei_raw, int N) {
    int i = blockIdx.x * blockDim.x + threadIdx.x;
    if (i < N) g_cnt[i] = 0;
    if (i == 0) {
        int any = 0;
        for (int j = 0; j < 64; j++) any |= ei_raw[2 * j + 1];
        g_is64 = (any == 0) ? 1 : 0;
    }
}

// Count in-degree; int32 path vectorized 4 edges/thread via int4.
__global__ void k_count(const void* __restrict__ ei_raw, int E, int N) {
    int t = blockIdx.x * blockDim.x + threadIdx.x;
    int e0 = t * 4;
    if (e0 >= E) return;
    if (g_is64) {
        const long long* ei = (const long long*)ei_raw;
        for (int j = 0; j < 4 && e0 + j < E; j++) {
            int c = (int)ei[(size_t)E + e0 + j];
            if ((unsigned)c < (unsigned)N) atomicAdd(&g_cnt[c], 1);
        }
    } else {
        const int* ei = (const int*)ei_raw;
        if (e0 + 4 <= E) {
            int4 c4 = *(const int4*)(ei + (size_t)E + e0);
            if ((unsigned)c4.x < (unsigned)N) atomicAdd(&g_cnt[c4.x], 1);
            if ((unsigned)c4.y < (unsigned)N) atomicAdd(&g_cnt[c4.y], 1);
            if ((unsigned)c4.z < (unsigned)N) atomicAdd(&g_cnt[c4.z], 1);
            if ((unsigned)c4.w < (unsigned)N) atomicAdd(&g_cnt[c4.w], 1);
        } else {
            for (int j = 0; e0 + j < E; j++) {
                int c = ei[(size_t)E + e0 + j];
                if ((unsigned)c < (unsigned)N) atomicAdd(&g_cnt[c], 1);
            }
        }
    }
}

__global__ void k_dinv(int N) {
    int i = blockIdx.x * blockDim.x + threadIdx.x;
    if (i < N) g_dinv[i] = rsqrtf((float)(g_cnt[i] + 1));   // +1 self loop
}

__global__ void __launch_bounds__(SCAN_B) k_scan_partial(int N) {
    __shared__ int red[SCAN_B / 32];
    int b = blockIdx.x, tid = threadIdx.x;
    int i = b * SCAN_B + tid;
    int v = (i < N) ? g_cnt[i] : 0;
    for (int o = 16; o > 0; o >>= 1) v += __shfl_down_sync(0xffffffffu, v, o);
    if ((tid & 31) == 0) red[tid >> 5] = v;
    __syncthreads();
    if (tid < SCAN_B / 32) {
        int s = red[tid];
        for (int o = (SCAN_B / 64); o > 0; o >>= 1) s += __shfl_down_sync(0xffffu, s, o);
        if (tid == 0) g_bsum[b] = s;
    }
}

__global__ void __launch_bounds__(256) k_scan_blk(int nb, int N) {
    __shared__ int sh[256];
    int tid = threadIdx.x;
    int v = (tid < nb) ? g_bsum[tid] : 0;
    sh[tid] = v;
    __syncthreads();
    for (int o = 1; o < 256; o <<= 1) {
        int t = (tid >= o) ? sh[tid - o] : 0;
        __syncthreads();
        sh[tid] += t;
        __syncthreads();
    }
    if (tid < nb) g_boff[tid] = sh[tid] - v;       // exclusive
    if (tid == 255) g_rowstart[N] = sh[255];       // total
}

__global__ void __launch_bounds__(SCAN_B) k_scan_apply(int N) {
    __shared__ int sh[SCAN_B];
    int b = blockIdx.x, tid = threadIdx.x;
    int i = b * SCAN_B + tid;
    int v = (i < N) ? g_cnt[i] : 0;
    sh[tid] = v;
    __syncthreads();
    for (int o = 1; o < SCAN_B; o <<= 1) {
        int t = (tid >= o) ? sh[tid - o] : 0;
        __syncthreads();
        sh[tid] += t;
        __syncthreads();
    }
    if (i < N) {
        int base = g_boff[b] + sh[tid] - v;        // exclusive prefix
        g_rowstart[i] = base;
        g_cursor[i]   = base;
    }
}

__global__ void k_fill(const void* __restrict__ ei_raw, int E, int N) {
    int e = blockIdx.x * blockDim.x + threadIdx.x;
    if (e >= E) return;
    int r, c;
    if (g_is64) {
        const long long* ei = (const long long*)ei_raw;
        r = (int)ei[e];
        c = (int)ei[(size_t)E + e];
    } else {
        const int* ei = (const int*)ei_raw;
        r = ei[e];
        c = ei[(size_t)E + e];
    }
    if ((unsigned)r >= (unsigned)N || (unsigned)c >= (unsigned)N) return;
    int pos = atomicAdd(&g_cursor[c], 1);
    g_csr[pos] = r;
}

// ---------------- helpers ----------------------------------------------------

__device__ __forceinline__ uint2 pack4h(float a, float b, float c, float d) {
    __half2 h01 = __floats2half2_rn(a, b);
    __half2 h23 = __floats2half2_rn(c, d);
    uint2 u;
    u.x = reinterpret_cast<unsigned&>(h01);
    u.y = reinterpret_cast<unsigned&>(h23);
    return u;
}
__device__ __forceinline__ void unpack4h(uint2 u, float4& o) {
    float2 f0 = __half22float2(reinterpret_cast<__half2&>(u.x));
    float2 f1 = __half22float2(reinterpret_cast<__half2&>(u.y));
    o.x = f0.x; o.y = f0.y; o.z = f1.x; o.w = f1.y;
}

// ---------------- tensor-core GEMMs (fp16 m16n16k16, fp32 accumulate) --------

// GEMM1: g_h1h[n, fh..fh+63] = fp16((x[n]*dinv[n]) @ W1[:, fh..fh+63])
__global__ void __launch_bounds__(256) k_gemm1(const float* __restrict__ x,
                                               const float* __restrict__ W1, int N) {
    __shared__ __align__(16) char smem_raw[SMEM_BYTES];
    __half* As = (__half*)smem_raw;
    __half* Bs = (__half*)(smem_raw + A_BYTES);
    float*  Cs = (float*)smem_raw;
    int tid = threadIdx.x;
    int fh = blockIdx.y * 64;
    int base = blockIdx.x * 64;
    int wid = tid >> 5;
    int tm = (wid >> 1) * 16;
    int tn = (wid & 1) * 32;

    for (int idx = tid; idx < 2048; idx += 256) {
        int r = idx >> 5, c = idx & 31;
        int n = base + r;
        float4 v = make_float4(0.f, 0.f, 0.f, 0.f);
        float d = 0.f;
        if (n < N) {
            v = *(const float4*)(x + (size_t)n * F1 + 4 * c);
            d = g_dinv[n];
        }
        *(uint2*)&As[r * A_STRIDE + 4 * c] = pack4h(v.x * d, v.y * d, v.z * d, v.w * d);
    }
    for (int idx = tid; idx < 2048; idx += 256) {
        int r = idx >> 4, c = idx & 15;
        float4 v = *(const float4*)(W1 + (size_t)r * F1 + fh + 4 * c);
        *(uint2*)&Bs[r * B_STRIDE + 4 * c] = pack4h(v.x, v.y, v.z, v.w);
    }
    __syncthreads();

    wmma::fragment<wmma::accumulator, 16, 16, 16, float> c0, c1;
    wmma::fill_fragment(c0, 0.f);
    wmma::fill_fragment(c1, 0.f);
    #pragma unroll
    for (int k = 0; k < 8; k++) {
        wmma::fragment<wmma::matrix_a, 16, 16, 16, __half, wmma::row_major> a;
        wmma::fragment<wmma::matrix_b, 16, 16, 16, __half, wmma::row_major> b0, b1;
        wmma::load_matrix_sync(a, &As[tm * A_STRIDE + k * 16], A_STRIDE);
        wmma::load_matrix_sync(b0, &Bs[(k * 16) * B_STRIDE + tn], B_STRIDE);
        wmma::load_matrix_sync(b1, &Bs[(k * 16) * B_STRIDE + tn + 16], B_STRIDE);
        wmma::mma_sync(c0, a, b0, c0);
        wmma::mma_sync(c1, a, b1, c1);
    }
    __syncthreads();
    wmma::store_matrix_sync(&Cs[tm * C_STRIDE + tn], c0, C_STRIDE, wmma::mem_row_major);
    wmma::store_matrix_sync(&Cs[tm * C_STRIDE + tn + 16], c1, C_STRIDE, wmma::mem_row_major);
    __syncthreads();
    int fo = fh >> 2;
    for (int idx = tid; idx < 1024; idx += 256) {
        int r = idx >> 4, q = idx & 15;
        int n = base + r;
        if (n < N) {
            float4 v = *(const float4*)&Cs[r * C_STRIDE + 4 * q];
            g_h1h[(size_t)n * 32 + fo + q] = pack4h(v.x, v.y, v.z, v.w);
        }
    }
}

// GEMM2: g_h2h[n] = fp16((hidden[n]*dinv[n]) @ W2); hidden read as fp16.
__global__ void __launch_bounds__(256) k_gemm2(const float* __restrict__ W2, int N) {
    __shared__ __align__(16) char smem_raw[SMEM_BYTES];
    __half* As = (__half*)smem_raw;
    __half* Bs = (__half*)(smem_raw + A_BYTES);
    float*  Cs = (float*)smem_raw;
    int tid = threadIdx.x;
    int base = blockIdx.x * 64;
    int wid = tid >> 5;
    int tm = (wid >> 1) * 16;
    int tn = (wid & 1) * 32;

    for (int idx = tid; idx < 2048; idx += 256) {
        int r = idx >> 5, c = idx & 31;
        int n = base + r;
        float4 v = make_float4(0.f, 0.f, 0.f, 0.f);
        float d = 0.f;
        if (n < N) {
            unpack4h(g_hidh[(size_t)n * 32 + c], v);
            d = g_dinv[n];
        }
        *(uint2*)&As[r * A_STRIDE + 4 * c] = pack4h(v.x * d, v.y * d, v.z * d, v.w * d);
    }
    for (int idx = tid; idx < 2048; idx += 256) {
        int r = idx >> 4, c = idx & 15;
        float4 v = *(const float4*)(W2 + (size_t)r * F2 + 4 * c);
        *(uint2*)&Bs[r * B_STRIDE + 4 * c] = pack4h(v.x, v.y, v.z, v.w);
    }
    __syncthreads();

    wmma::fragment<wmma::accumulator, 16, 16, 16, float> c0, c1;
    wmma::fill_fragment(c0, 0.f);
    wmma::fill_fragment(c1, 0.f);
    #pragma unroll
    for (int k = 0; k < 8; k++) {
        wmma::fragment<wmma::matrix_a, 16, 16, 16, __half, wmma::row_major> a;
        wmma::fragment<wmma::matrix_b, 16, 16, 16, __half, wmma::row_major> b0, b1;
        wmma::load_matrix_sync(a, &As[tm * A_STRIDE + k * 16], A_STRIDE);
        wmma::load_matrix_sync(b0, &Bs[(k * 16) * B_STRIDE + tn], B_STRIDE);
        wmma::load_matrix_sync(b1, &Bs[(k * 16) * B_STRIDE + tn + 16], B_STRIDE);
        wmma::mma_sync(c0, a, b0, c0);
        wmma::mma_sync(c1, a, b1, c1);
    }
    __syncthreads();
    wmma::store_matrix_sync(&Cs[tm * C_STRIDE + tn], c0, C_STRIDE, wmma::mem_row_major);
    wmma::store_matrix_sync(&Cs[tm * C_STRIDE + tn + 16], c1, C_STRIDE, wmma::mem_row_major);
    __syncthreads();
    for (int idx = tid; idx < 1024; idx += 256) {
        int r = idx >> 4, q = idx & 15;
        int n = base + r;
        if (n < N) {
            float4 v = *(const float4*)&Cs[r * C_STRIDE + 4 * q];
            g_h2h[(size_t)n * 16 + q] = pack4h(v.x, v.y, v.z, v.w);
        }
    }
}

// ---------------- aggregation kernels ----------------------------------------

#define ACC4(u) do { float2 p; \
    p = __half22float2(reinterpret_cast<__half2&>((u).x)); acc.x += p.x; acc.y += p.y; \
    p = __half22float2(reinterpret_cast<__half2&>((u).y)); acc.z += p.x; acc.w += p.y; } while (0)

// Aggregate layer 1: warp per node, 8-deep gather unroll, fp16 in, fp16 out.
__global__ void __launch_bounds__(256) k_agg1(const float* __restrict__ b1, int N) {
    int lane  = threadIdx.x & 31;
    int warp  = (blockIdx.x * blockDim.x + threadIdx.x) >> 5;
    int nwarp = (gridDim.x * blockDim.x) >> 5;
    float bx = b1[4 * lane + 0], by = b1[4 * lane + 1];
    float bz = b1[4 * lane + 2], bw = b1[4 * lane + 3];
    for (int n = warp; n < N; n += nwarp) {
        float4 acc;
        unpack4h(g_h1h[(size_t)n * 32 + lane], acc);    // self loop
        int s = g_rowstart[n], e = g_rowstart[n + 1];
        int i = s;
        for (; i + 8 <= e; i += 8) {
            int i0 = g_csr[i],     i1 = g_csr[i + 1], i2 = g_csr[i + 2], i3 = g_csr[i + 3];
            int i4 = g_csr[i + 4], i5 = g_csr[i + 5], i6 = g_csr[i + 6], i7 = g_csr[i + 7];
            uint2 u0 = g_h1h[(size_t)i0 * 32 + lane];
            uint2 u1 = g_h1h[(size_t)i1 * 32 + lane];
            uint2 u2 = g_h1h[(size_t)i2 * 32 + lane];
            uint2 u3 = g_h1h[(size_t)i3 * 32 + lane];
            uint2 u4 = g_h1h[(size_t)i4 * 32 + lane];
            uint2 u5 = g_h1h[(size_t)i5 * 32 + lane];
            uint2 u6 = g_h1h[(size_t)i6 * 32 + lane];
            uint2 u7 = g_h1h[(size_t)i7 * 32 + lane];
            ACC4(u0); ACC4(u1); ACC4(u2); ACC4(u3);
            ACC4(u4); ACC4(u5); ACC4(u6); ACC4(u7);
        }
        for (; i + 4 <= e; i += 4) {
            int i0 = g_csr[i], i1 = g_csr[i + 1], i2 = g_csr[i + 2], i3 = g_csr[i + 3];
            uint2 u0 = g_h1h[(size_t)i0 * 32 + lane];
            uint2 u1 = g_h1h[(size_t)i1 * 32 + lane];
            uint2 u2 = g_h1h[(size_t)i2 * 32 + lane];
            uint2 u3 = g_h1h[(size_t)i3 * 32 + lane];
            ACC4(u0); ACC4(u1); ACC4(u2); ACC4(u3);
        }
        for (; i < e; i++) {
            uint2 u = g_h1h[(size_t)g_csr[i] * 32 + lane];
            ACC4(u);
        }
        float dn = g_dinv[n];
        float ox = fmaxf(fmaf(dn, acc.x, bx), 0.f);
        float oy = fmaxf(fmaf(dn, acc.y, by), 0.f);
        float oz = fmaxf(fmaf(dn, acc.z, bz), 0.f);
        float ow = fmaxf(fmaf(dn, acc.w, bw), 0.f);
        g_hidh[(size_t)n * 32 + lane] = pack4h(ox, oy, oz, ow);
    }
}

// Aggregate layer 2: warp per node, 8-deep gather unroll, fp32 out.
__global__ void __launch_bounds__(256) k_agg2(const float* __restrict__ b2,
                                              float* __restrict__ out, int N) {
    int lane  = threadIdx.x & 31;
    int warp  = (blockIdx.x * blockDim.x + threadIdx.x) >> 5;
    int nwarp = (gridDim.x * blockDim.x) >> 5;
    float bx = b2[2 * lane + 0], by = b2[2 * lane + 1];
    const __half2* h2p = (const __half2*)g_h2h;
    for (int n = warp; n < N; n += nwarp) {
        float2 acc = __half22float2(h2p[(size_t)n * 32 + lane]);   // self loop
        int s = g_rowstart[n], e = g_rowstart[n + 1];
        int i = s;
        for (; i + 8 <= e; i += 8) {
            int i0 = g_csr[i],     i1 = g_csr[i + 1], i2 = g_csr[i + 2], i3 = g_csr[i + 3];
            int i4 = g_csr[i + 4], i5 = g_csr[i + 5], i6 = g_csr[i + 6], i7 = g_csr[i + 7];
            float2 v0 = __half22float2(h2p[(size_t)i0 * 32 + lane]);
            float2 v1 = __half22float2(h2p[(size_t)i1 * 32 + lane]);
            float2 v2 = __half22float2(h2p[(size_t)i2 * 32 + lane]);
            float2 v3 = __half22float2(h2p[(size_t)i3 * 32 + lane]);
            float2 v4 = __half22float2(h2p[(size_t)i4 * 32 + lane]);
            float2 v5 = __half22float2(h2p[(size_t)i5 * 32 + lane]);
            float2 v6 = __half22float2(h2p[(size_t)i6 * 32 + lane]);
            float2 v7 = __half22float2(h2p[(size_t)i7 * 32 + lane]);
            acc.x += ((v0.x + v1.x) + (v2.x + v3.x)) + ((v4.x + v5.x) + (v6.x + v7.x));
            acc.y += ((v0.y + v1.y) + (v2.y + v3.y)) + ((v4.y + v5.y) + (v6.y + v7.y));
        }
        for (; i + 4 <= e; i += 4) {
            int i0 = g_csr[i], i1 = g_csr[i + 1], i2 = g_csr[i + 2], i3 = g_csr[i + 3];
            float2 v0 = __half22float2(h2p[(size_t)i0 * 32 + lane]);
            float2 v1 = __half22float2(h2p[(size_t)i1 * 32 + lane]);
            float2 v2 = __half22float2(h2p[(size_t)i2 * 32 + lane]);
            float2 v3 = __half22float2(h2p[(size_t)i3 * 32 + lane]);
            acc.x += (v0.x + v1.x) + (v2.x + v3.x);
            acc.y += (v0.y + v1.y) + (v2.y + v3.y);
        }
        for (; i < e; i++) {
            float2 v = __half22float2(h2p[(size_t)g_csr[i] * 32 + lane]);
            acc.x += v.x; acc.y += v.y;
        }
        float dn = g_dinv[n];
        out[(size_t)n * F2 + 2 * lane + 0] = fmaf(dn, acc.x, bx);
        out[(size_t)n * F2 + 2 * lane + 1] = fmaf(dn, acc.y, by);
    }
}

// ---------------- launcher ---------------------------------------------------

static cudaStream_t aux_stream() {
    static cudaStream_t s = nullptr;
    if (!s) cudaStreamCreateWithFlags(&s, cudaStreamNonBlocking);
    return s;
}
static cudaEvent_t aux_event(int which) {
    static cudaEvent_t ev[2] = {nullptr, nullptr};
    if (!ev[which]) cudaEventCreateWithFlags(&ev[which], cudaEventDisableTiming);
    return ev[which];
}

extern "C" void kernel_launch(void* const* d_in, const int* in_sizes, int n_in,
                              void* d_out, int out_size) {
    const float* x  = (const float*)d_in[0];
    const void*  ei = d_in[1];                 // int32 or int64 — probed on device
    // d_in[2] = edge_weight (unused: reference overwrites with ones)
    const float* W1 = (const float*)d_in[3];
    const float* b1 = (const float*)d_in[4];
    const float* W2 = (const float*)d_in[5];
    const float* b2 = (const float*)d_in[6];
    float*       out = (float*)d_out;

    int N = in_sizes[0] / F1;
    int E = in_sizes[1] / 2;
    if (N > NMAX) N = NMAX;
    if (E > EMAX) E = EMAX;
    int nb = (N + SCAN_B - 1) / SCAN_B;
    int ntile = (N + 63) / 64;

    cudaStream_t s2 = aux_stream();
    cudaEvent_t evFork = aux_event(0);
    cudaEvent_t evJoin = aux_event(1);

    // --- serial prefix: dtype probe + zero counts, degree counts, dinv ---
    k_init<<<(N + 255) / 256, 256>>>((const int*)ei, N);
    k_count<<<((E + 3) / 4 + 255) / 256, 256>>>(ei, E, N);
    k_dinv<<<(N + 255) / 256, 256>>>(N);

    // --- fork: GEMM1 (needs only dinv) runs concurrent with CSR build ---
    cudaEventRecord(evFork, 0);
    cudaStreamWaitEvent(s2, evFork, 0);
    dim3 g1(ntile, 2);
    k_gemm1<<<g1, 256, 0, s2>>>(x, W1, N);
    cudaEventRecord(evJoin, s2);

    k_scan_partial<<<nb, SCAN_B>>>(N);
    k_scan_blk<<<1, 256>>>(nb, N);
    k_scan_apply<<<nb, SCAN_B>>>(N);
    k_fill<<<(E + 255) / 256, 256>>>(ei, E, N);

    // --- join: aggregation needs both CSR and h1s ---
    cudaStreamWaitEvent(0, evJoin, 0);
    k_agg1<<<(N + 7) / 8, 256>>>(b1, N);
    k_gemm2<<<ntile, 256>>>(W2, N);
    k_agg2<<<(N + 7) / 8, 256>>>(b2, out, N);
}